// round 1
// baseline (speedup 1.0000x reference)
#include <cuda_runtime.h>
#include <cstdint>

#define B 4
#define S 2048
#define H 4
#define DH 48
#define D 192
#define TQ 32
#define TK 64
#define NT (S/TK)
#define NEG_INF -1000000000.0f

// Scratch (device globals: allocation-free kernel_launch)
__device__ float g_q[B*S*D];
__device__ float g_k[B*S*D];
__device__ float g_v[B*S*D];
__device__ float g_ctx[B*S*D];
__device__ float g_E[B*H*S*S];      // 256MB: unnormalized exp(logits)
__device__ float g_Linv[B*H*S];     // 1/rowsum

// ---------- packed fp32x2 helpers (Blackwell FFMA2) ----------
__device__ __forceinline__ unsigned long long pack2(float x, float y) {
    unsigned long long r;
    asm("mov.b64 %0, {%1,%2};" : "=l"(r) : "f"(x), "f"(y));
    return r;
}
__device__ __forceinline__ void unpack2(unsigned long long v, float& x, float& y) {
    asm("mov.b64 {%0,%1}, %2;" : "=f"(x), "=f"(y) : "l"(v));
}
__device__ __forceinline__ void ffma2(unsigned long long& d, unsigned long long a, unsigned long long b) {
    asm("fma.rn.f32x2 %0, %1, %2, %0;" : "+l"(d) : "l"(a), "l"(b));
}

// ---------- projection GEMM: Y[r][j] = sum_k X[r][k] * W[j][k] ----------
// 32 rows per block, full 192 cols. W transposed into smem for f32x2 pairs.
#define PROJ_SMEM ((192*33 + 192*194)*4)
__global__ __launch_bounds__(256) void proj_kernel(const float* __restrict__ X,
                                                   const float* __restrict__ W,
                                                   float* __restrict__ Y) {
    extern __shared__ float sm[];
    float* sXT = sm;            // [192][33]  (k-major, transposed)
    float* sWT = sm + 192*33;   // [192][194] (k-major, transposed)
    const int tid = threadIdx.x;
    const int r0 = blockIdx.x * 32;

    const float4* w4 = reinterpret_cast<const float4*>(W);
    #pragma unroll
    for (int k = 0; k < 36; k++) {
        int idx = tid + k*256;            // 9216 float4
        int j = idx / 48, c = idx % 48;
        float4 v = w4[idx];
        sWT[(c*4+0)*194 + j] = v.x;
        sWT[(c*4+1)*194 + j] = v.y;
        sWT[(c*4+2)*194 + j] = v.z;
        sWT[(c*4+3)*194 + j] = v.w;
    }
    const float4* x4 = reinterpret_cast<const float4*>(X + (size_t)r0 * D);
    #pragma unroll
    for (int k = 0; k < 6; k++) {
        int idx = tid + k*256;            // 1536 float4
        int r = idx / 48, c = idx % 48;
        float4 v = x4[idx];
        sXT[(c*4+0)*33 + r] = v.x;
        sXT[(c*4+1)*33 + r] = v.y;
        sXT[(c*4+2)*33 + r] = v.z;
        sXT[(c*4+3)*33 + r] = v.w;
    }
    __syncthreads();

    const int r  = tid & 31;
    const int cg = tid >> 5;              // 0..7 -> 24-col strip
    unsigned long long acc[12];
    #pragma unroll
    for (int c = 0; c < 12; c++) acc[c] = 0ull;

    #pragma unroll 4
    for (int kk = 0; kk < 192; kk++) {
        float xv = sXT[kk*33 + r];                       // conflict-free
        unsigned long long x2 = pack2(xv, xv);
        const unsigned long long* wrow =
            reinterpret_cast<const unsigned long long*>(&sWT[kk*194 + cg*24]); // broadcast
        #pragma unroll
        for (int c = 0; c < 12; c++) ffma2(acc[c], x2, wrow[c]);
    }
    float* dst = Y + (size_t)(r0 + r) * D + cg*24;
    #pragma unroll
    for (int c = 0; c < 12; c++) {
        float x, y; unpack2(acc[c], x, y);
        dst[2*c] = x; dst[2*c+1] = y;
    }
}

// ---------- attention: per (b, q-tile of 32), all 4 heads, single pass over K/V ----------
#define ATTN_SMEM ((TQ*200 + TK*200 + H*TQ*65 + H*TQ)*4)
__global__ __launch_bounds__(256) void attn_kernel(const int* __restrict__ gmask,
                                                   const float* __restrict__ gbias) {
    extern __shared__ float sm[];
    float* sQ  = sm;                     // [TQ][200]
    float* sKV = sQ + TQ*200;            // [TK][200] (K then V, reused)
    float* sEB = sKV + TK*200;           // [H][TQ][65]: masked bias, then exp(logit)
    float* sL  = sEB + H*TQ*65;          // [H*TQ] running exp-sums

    const int tid = threadIdx.x;
    const int b  = blockIdx.x;
    const int q0 = blockIdx.y * TQ;

    if (tid < H*TQ) sL[tid] = 0.f;

    { // load Q tile
        const float4* src = reinterpret_cast<const float4*>(g_q + (size_t)(b*S + q0) * D);
        #pragma unroll
        for (int k = 0; k < 6; k++) {
            int idx = tid + k*256;
            int r = idx / 48, c = idx % 48;
            float4 v = src[idx];
            float* dst = &sQ[r*200 + c*4];
            dst[0]=v.x; dst[1]=v.y; dst[2]=v.z; dst[3]=v.w;
        }
    }
    __syncthreads();

    // S-phase identity: thread owns (h, qi), half the j-range
    const int qi = tid & 31;
    const int h  = (tid >> 5) & 3;
    const int jh = tid >> 7;             // 0/1
    unsigned long long qreg[24];
    #pragma unroll
    for (int kk = 0; kk < 24; kk++)
        qreg[kk] = *reinterpret_cast<const unsigned long long*>(&sQ[qi*200 + h*DH + 2*kk]);

    // O-phase identity: thread owns (qi, 12 col-pairs ddp = ddb+8k)
    const int ddb = tid >> 5;            // 0..7
    unsigned long long oacc[12];
    #pragma unroll
    for (int k = 0; k < 12; k++) oacc[k] = 0ull;

    for (int t = 0; t < NT; t++) {
        const int j0 = t * TK;
        { // load K tile + stage masked bias
            const float4* src = reinterpret_cast<const float4*>(g_k + (size_t)(b*S + j0) * D);
            #pragma unroll
            for (int k = 0; k < 12; k++) {
                int idx = tid + k*256;
                int r = idx / 48, c = idx % 48;
                float4 v = src[idx];
                float* dst = &sKV[r*200 + c*4];
                dst[0]=v.x; dst[1]=v.y; dst[2]=v.z; dst[3]=v.w;
            }
            #pragma unroll
            for (int k = 0; k < 8; k++) {
                int p = tid + k*256;              // 2048 (qi,j) pairs
                int r = p >> 6, j = p & 63;
                int m = gmask[(size_t)(b*S + q0 + r) * S + j0 + j];
                #pragma unroll
                for (int hh = 0; hh < H; hh++) {
                    float bv = (m == 0) ? NEG_INF
                                        : gbias[(size_t)(hh*S + q0 + r) * S + j0 + j];
                    sEB[(hh*TQ + r)*65 + j] = bv;
                }
            }
        }
        __syncthreads();
        { // S phase: logits + exp, in-place into sEB
            float lloc = 0.f;
            #pragma unroll 2
            for (int jj = 0; jj < 32; jj++) {
                int j = jh*32 + jj;
                unsigned long long acc = 0ull;
                const unsigned long long* krow =
                    reinterpret_cast<const unsigned long long*>(&sKV[j*200 + h*DH]); // broadcast
                #pragma unroll
                for (int kk = 0; kk < 24; kk++) ffma2(acc, qreg[kk], krow[kk]);
                float ax, ay; unpack2(acc, ax, ay);
                float sv = ax + ay + sEB[(h*TQ + qi)*65 + j];
                float e = __expf(sv);             // no max-sub needed: |logit| < 45
                sEB[(h*TQ + qi)*65 + j] = e;
                lloc += e;
            }
            atomicAdd(&sL[h*TQ + qi], lloc);
        }
        __syncthreads();
        { // stream e to gmem scratch (coalesced) + load V tile over K
            #pragma unroll
            for (int k = 0; k < 32; k++) {
                int idx = tid + k*256;            // 8192 values
                int j = idx & 63, r = (idx >> 6) & 31, hh = idx >> 11;
                g_E[(size_t)((b*H + hh)*S + q0 + r) * S + j0 + j] = sEB[(hh*TQ + r)*65 + j];
            }
            const float4* src = reinterpret_cast<const float4*>(g_v + (size_t)(b*S + j0) * D);
            #pragma unroll
            for (int k = 0; k < 12; k++) {
                int idx = tid + k*256;
                int r = idx / 48, c = idx % 48;
                float4 v = src[idx];
                float* dst = &sKV[r*200 + c*4];
                dst[0]=v.x; dst[1]=v.y; dst[2]=v.z; dst[3]=v.w;
            }
        }
        __syncthreads();
        { // O phase: oacc += e * V
            #pragma unroll 2
            for (int j = 0; j < TK; j++) {
                unsigned long long e2[4];
                #pragma unroll
                for (int hh = 0; hh < 4; hh++) {
                    float e = sEB[(hh*TQ + qi)*65 + j];    // stride 65: conflict-free
                    e2[hh] = pack2(e, e);
                }
                #pragma unroll
                for (int k = 0; k < 12; k++) {
                    int ddp = ddb + 8*k;                   // hh == k/3 (compile-time)
                    unsigned long long v2 =
                        *reinterpret_cast<const unsigned long long*>(&sKV[j*200 + 2*ddp]); // broadcast
                    ffma2(oacc[k], e2[k/3], v2);
                }
            }
        }
        __syncthreads();
    }

    // finalize: 1/l to gmem, scaled O to ctx
    if (tid < H*TQ) {
        int hh = tid >> 5, r = tid & 31;
        g_Linv[(b*H + hh)*S + q0 + r] = 1.f / sL[tid];
    }
    #pragma unroll
    for (int k = 0; k < 12; k++) {
        int ddp = ddb + 8*k;
        float inv = 1.f / sL[(k/3)*TQ + qi];
        float x, y; unpack2(oacc[k], x, y);
        float2 o; o.x = x * inv; o.y = y * inv;
        *reinterpret_cast<float2*>(&g_ctx[(size_t)(b*S + q0 + qi) * D + 2*ddp]) = o;
    }
}

// ---------- mean over heads: om[b,qi,j] = 0.25 * sum_h e[b,h,qi,j] / l[b,h,qi] ----------
__global__ __launch_bounds__(256) void mean_kernel(float* __restrict__ om) {
    const int row = blockIdx.x;          // b*S + qi
    const int b = row >> 11, qi = row & 2047;
    const int tid = threadIdx.x;
    const float4* e0 = reinterpret_cast<const float4*>(&g_E[(size_t)((b*H + 0)*S + qi) * S]);
    const float4* e1 = reinterpret_cast<const float4*>(&g_E[(size_t)((b*H + 1)*S + qi) * S]);
    const float4* e2 = reinterpret_cast<const float4*>(&g_E[(size_t)((b*H + 2)*S + qi) * S]);
    const float4* e3 = reinterpret_cast<const float4*>(&g_E[(size_t)((b*H + 3)*S + qi) * S]);
    const float il0 = g_Linv[(b*H + 0)*S + qi];
    const float il1 = g_Linv[(b*H + 1)*S + qi];
    const float il2 = g_Linv[(b*H + 2)*S + qi];
    const float il3 = g_Linv[(b*H + 3)*S + qi];
    float4* dst = reinterpret_cast<float4*>(om + (size_t)row * S);
    #pragma unroll
    for (int k = 0; k < 2; k++) {
        int i = tid + k*256;             // 512 float4 per row
        float4 a = e0[i], c = e1[i], d2 = e2[i], e = e3[i];
        float4 r;
        r.x = 0.25f * (a.x*il0 + c.x*il1 + d2.x*il2 + e.x*il3);
        r.y = 0.25f * (a.y*il0 + c.y*il1 + d2.y*il2 + e.y*il3);
        r.z = 0.25f * (a.z*il0 + c.z*il1 + d2.z*il2 + e.z*il3);
        r.w = 0.25f * (a.w*il0 + c.w*il1 + d2.w*il2 + e.w*il3);
        dst[i] = r;
    }
}

extern "C" void kernel_launch(void* const* d_in, const int* in_sizes, int n_in,
                              void* d_out, int out_size) {
    (void)in_sizes; (void)n_in; (void)out_size;
    const float* query = (const float*)d_in[0];
    const float* key   = (const float*)d_in[1];
    const float* value = (const float*)d_in[2];
    const int*   mask  = (const int*)  d_in[3];
    const float* bias  = (const float*)d_in[4];
    const float* Wq    = (const float*)d_in[5];
    const float* Wk    = (const float*)d_in[6];
    const float* Wv    = (const float*)d_in[7];
    const float* Wo    = (const float*)d_in[8];

    float* out = (float*)d_out;                 // [B,S,D]
    float* om  = out + B*S*D;                   // [B,S,S] mean weights

    float *pq, *pk, *pv, *pctx;
    cudaGetSymbolAddress((void**)&pq,   g_q);
    cudaGetSymbolAddress((void**)&pk,   g_k);
    cudaGetSymbolAddress((void**)&pv,   g_v);
    cudaGetSymbolAddress((void**)&pctx, g_ctx);

    cudaFuncSetAttribute(proj_kernel, cudaFuncAttributeMaxDynamicSharedMemorySize, PROJ_SMEM);
    cudaFuncSetAttribute(attn_kernel, cudaFuncAttributeMaxDynamicSharedMemorySize, ATTN_SMEM);

    proj_kernel<<<256, 256, PROJ_SMEM>>>(query, Wq, pq);
    proj_kernel<<<256, 256, PROJ_SMEM>>>(key,   Wk, pk);
    proj_kernel<<<256, 256, PROJ_SMEM>>>(value, Wv, pv);
    attn_kernel<<<dim3(B, S/TQ), 256, ATTN_SMEM>>>(mask, bias);
    mean_kernel<<<B*S, 256>>>(om);
    proj_kernel<<<256, 256, PROJ_SMEM>>>(pctx, Wo, out);
}

// round 2
// speedup vs baseline: 1.5536x; 1.5536x over previous
#include <cuda_runtime.h>
#include <cstdint>

#define B 4
#define S 2048
#define H 4
#define DH 48
#define D 192
#define TQ 32
#define TK 64
#define NT (S/TK)
#define NEG_INF -1000000000.0f

// Scratch (device globals: allocation-free kernel_launch)
__device__ float g_q[B*S*D];
__device__ float g_k[B*S*D];
__device__ float g_v[B*S*D];
__device__ float g_ctx[B*S*D];
__device__ float g_E[(size_t)B*H*S*S];   // 256MB unnormalized exp(logits)
__device__ float g_Linv[B*H*S];

// ---------- packed fp32x2 helpers ----------
__device__ __forceinline__ unsigned long long pack2(float x, float y) {
    unsigned long long r;
    asm("mov.b64 %0, {%1,%2};" : "=l"(r) : "f"(x), "f"(y));
    return r;
}
__device__ __forceinline__ void unpack2(unsigned long long v, float& x, float& y) {
    asm("mov.b64 {%0,%1}, %2;" : "=f"(x), "=f"(y) : "l"(v));
}
__device__ __forceinline__ void ffma2(unsigned long long& d, unsigned long long a, unsigned long long b) {
    asm("fma.rn.f32x2 %0, %1, %2, %0;" : "+l"(d) : "l"(a), "l"(b));
}

// ---------- projection GEMM (unchanged from R1) ----------
#define PROJ_SMEM ((192*33 + 192*194)*4)
__global__ __launch_bounds__(256) void proj_kernel(const float* __restrict__ X,
                                                   const float* __restrict__ W,
                                                   float* __restrict__ Y) {
    extern __shared__ float sm[];
    float* sXT = sm;            // [192][33]
    float* sWT = sm + 192*33;   // [192][194]
    const int tid = threadIdx.x;
    const int r0 = blockIdx.x * 32;

    const float4* w4 = reinterpret_cast<const float4*>(W);
    #pragma unroll
    for (int k = 0; k < 36; k++) {
        int idx = tid + k*256;
        int j = idx / 48, c = idx % 48;
        float4 v = w4[idx];
        sWT[(c*4+0)*194 + j] = v.x;
        sWT[(c*4+1)*194 + j] = v.y;
        sWT[(c*4+2)*194 + j] = v.z;
        sWT[(c*4+3)*194 + j] = v.w;
    }
    const float4* x4 = reinterpret_cast<const float4*>(X + (size_t)r0 * D);
    #pragma unroll
    for (int k = 0; k < 6; k++) {
        int idx = tid + k*256;
        int r = idx / 48, c = idx % 48;
        float4 v = x4[idx];
        sXT[(c*4+0)*33 + r] = v.x;
        sXT[(c*4+1)*33 + r] = v.y;
        sXT[(c*4+2)*33 + r] = v.z;
        sXT[(c*4+3)*33 + r] = v.w;
    }
    __syncthreads();

    const int r  = tid & 31;
    const int cg = tid >> 5;
    unsigned long long acc[12];
    #pragma unroll
    for (int c = 0; c < 12; c++) acc[c] = 0ull;

    #pragma unroll 4
    for (int kk = 0; kk < 192; kk++) {
        float xv = sXT[kk*33 + r];
        unsigned long long x2 = pack2(xv, xv);
        const unsigned long long* wrow =
            reinterpret_cast<const unsigned long long*>(&sWT[kk*194 + cg*24]);
        #pragma unroll
        for (int c = 0; c < 12; c++) ffma2(acc[c], x2, wrow[c]);
    }
    float* dst = Y + (size_t)(r0 + r) * D + cg*24;
    #pragma unroll
    for (int c = 0; c < 12; c++) {
        float x, y; unpack2(acc[c], x, y);
        dst[2*c] = x; dst[2*c+1] = y;
    }
}

// ============================================================================
// Kernel A: E = exp(Q Kᵀ + bias, masked), rowsums -> g_Linv.
// Block = (b, 32-q tile), 256 threads. Thread tile: 4 qi × 8 j (32 dots).
// Thread map: jg = tid&7 (owns j = 4jg+{0..3} and 32+4jg+{0..3}),
//             rg = tid>>3 -> h = rg>>3, qi0 = (rg&7)*4.
// smem: Q[32][48 f4] + K[64][48 f4], XOR-swizzled (slot c ^ ((row>>2)&7)).
// ============================================================================
#define A_SMEM ((32*48 + 64*48)*16)
__global__ __launch_bounds__(256, 2) void logits_kernel(const int* __restrict__ gmask,
                                                        const float* __restrict__ gbias) {
    extern __shared__ float4 smA[];
    float4* sQ = smA;             // 32*48
    float4* sK = smA + 32*48;     // 64*48
    const int tid = threadIdx.x;
    const int b  = blockIdx.x;
    const int q0 = blockIdx.y * TQ;
    const int jg = tid & 7, rg = tid >> 3;
    const int h  = rg >> 3;
    const int qi0 = (rg & 7) * 4;
    const int swq = rg & 7;       // (qi>>2)&7, same for all 4 qi of this thread
    const int swk = jg;           // (j>>2)&7, same for all 8 j of this thread

    { // Q tile, swizzled
        const float4* gq = reinterpret_cast<const float4*>(g_q + (size_t)(b*S + q0) * D);
        #pragma unroll
        for (int k = 0; k < 6; k++) {
            int idx = tid + k*256;
            int r = idx / 48, c = idx - r*48;
            sQ[r*48 + (c ^ ((r>>2)&7))] = gq[idx];
        }
    }

    int kbase[8];
    #pragma unroll
    for (int m = 0; m < 8; m++) kbase[m] = (4*jg + (m&3) + 32*(m>>2)) * 48;
    int qbase[4];
    #pragma unroll
    for (int i = 0; i < 4; i++) qbase[i] = (qi0 + i) * 48;

    float lsum[4] = {0.f, 0.f, 0.f, 0.f};
    unsigned long long acc[4][8];

    for (int t = 0; t < NT; t++) {
        const int j0 = t * TK;
        __syncthreads();
        { // K tile, swizzled
            const float4* gk = reinterpret_cast<const float4*>(g_k + (size_t)(b*S + j0) * D);
            #pragma unroll
            for (int k = 0; k < 12; k++) {
                int idx = tid + k*256;
                int r = idx / 48, c = idx - r*48;
                sK[r*48 + (c ^ ((r>>2)&7))] = gk[idx];
            }
        }
        __syncthreads();

        #pragma unroll
        for (int i = 0; i < 4; i++)
            #pragma unroll
            for (int m = 0; m < 8; m++) acc[i][m] = 0ull;

        #pragma unroll
        for (int ch = 0; ch < 12; ch++) {
            const int cc = h*12 + ch;
            float4 qv[4];
            #pragma unroll
            for (int i = 0; i < 4; i++) qv[i] = sQ[qbase[i] + (cc ^ swq)];
            #pragma unroll
            for (int m = 0; m < 8; m++) {
                float4 kv = sK[kbase[m] + (cc ^ swk)];
                const unsigned long long* kp = reinterpret_cast<const unsigned long long*>(&kv);
                #pragma unroll
                for (int i = 0; i < 4; i++) {
                    const unsigned long long* qp = reinterpret_cast<const unsigned long long*>(&qv[i]);
                    ffma2(acc[i][m], qp[0], kp[0]);
                    ffma2(acc[i][m], qp[1], kp[1]);
                }
            }
        }

        // epilogue: bias/mask direct from gmem (coalesced float4/int4), exp, store E
        #pragma unroll
        for (int i = 0; i < 4; i++) {
            const int qi = q0 + qi0 + i;
            const int4*   mrow = reinterpret_cast<const int4*>(gmask + (size_t)(b*S + qi)*S + j0 + 4*jg);
            const float4* brow = reinterpret_cast<const float4*>(gbias + (size_t)(h*S + qi)*S + j0 + 4*jg);
            float4*       erow = reinterpret_cast<float4*>(g_E + (size_t)((b*H + h)*S + qi)*S + j0 + 4*jg);
            #pragma unroll
            for (int c = 0; c < 2; c++) {
                int4   mv = mrow[c*8];
                float4 bv = brow[c*8];
                float4 ev;
                float ax, ay;
                unpack2(acc[i][4*c+0], ax, ay); ev.x = __expf(mv.x ? ax + ay + bv.x : NEG_INF);
                unpack2(acc[i][4*c+1], ax, ay); ev.y = __expf(mv.y ? ax + ay + bv.y : NEG_INF);
                unpack2(acc[i][4*c+2], ax, ay); ev.z = __expf(mv.z ? ax + ay + bv.z : NEG_INF);
                unpack2(acc[i][4*c+3], ax, ay); ev.w = __expf(mv.w ? ax + ay + bv.w : NEG_INF);
                lsum[i] += (ev.x + ev.y) + (ev.z + ev.w);
                erow[c*8] = ev;
            }
        }
    }

    // rowsum reduce across the 8 jg lanes (consecutive lanes share rg)
    #pragma unroll
    for (int i = 0; i < 4; i++) {
        float v = lsum[i];
        v += __shfl_xor_sync(0xffffffffu, v, 1);
        v += __shfl_xor_sync(0xffffffffu, v, 2);
        v += __shfl_xor_sync(0xffffffffu, v, 4);
        if (jg == 0) g_Linv[(b*H + h)*S + q0 + qi0 + i] = 1.0f / v;
    }
}

// ============================================================================
// Kernel B: O = (E * Linv) @ V  -> g_ctx, fused mean-over-heads -> om.
// Block = (b, 32-q tile), 256 threads. Thread: h = tid>>6, qg = (tid>>2)&15,
// pg = tid&3; owns 2 qi × 6 dd-pairs of one head. smem: E[128][17 f4],
// V[64][48 f4] swizzled, Linv[128].
// ============================================================================
#define B_SMEM ((128*17 + 64*48)*16 + 128*4)
__global__ __launch_bounds__(256, 2) void pv_kernel(float* __restrict__ om) {
    extern __shared__ float4 smB[];
    float4* sE = smB;                 // 128*17
    float4* sV = smB + 128*17;        // 64*48
    float*  sLinv = reinterpret_cast<float*>(sV + 64*48);  // 128
    const int tid = threadIdx.x;
    const int b  = blockIdx.x;
    const int q0 = blockIdx.y * TQ;
    const int pg = tid & 3, qg = (tid >> 2) & 15, h = tid >> 6;
    const int c0 = h*12 + pg*3;
    const int ebase0 = (h*32 + 2*qg + 0) * 17;
    const int ebase1 = (h*32 + 2*qg + 1) * 17;

    if (tid < 128) sLinv[tid] = g_Linv[(b*H + (tid>>5))*S + q0 + (tid & 31)];

    unsigned long long oacc[2][6];
    #pragma unroll
    for (int u = 0; u < 2; u++)
        #pragma unroll
        for (int m = 0; m < 6; m++) oacc[u][m] = 0ull;

    for (int t = 0; t < NT; t++) {
        const int j0 = t * TK;
        __syncthreads();
        { // E tile (coalesced)
            #pragma unroll
            for (int k = 0; k < 8; k++) {
                int idx = tid + k*256;
                int r = idx >> 4, c4 = idx & 15;
                const float4* src = reinterpret_cast<const float4*>(
                    g_E + (size_t)((b*H + (r>>5))*S + q0 + (r&31))*S + j0 + 4*c4);
                sE[r*17 + c4] = src[0];
            }
            // V tile, swizzled
            const float4* gv = reinterpret_cast<const float4*>(g_v + (size_t)(b*S + j0) * D);
            #pragma unroll
            for (int k = 0; k < 12; k++) {
                int idx = tid + k*256;
                int r = idx / 48, c = idx - r*48;
                sV[r*48 + (c ^ ((r>>2)&7))] = gv[idx];
            }
        }
        __syncthreads();

        { // mean-over-heads output tile (coalesced write)
            #pragma unroll
            for (int k = 0; k < 2; k++) {
                int idx = tid + k*256;
                int qi = idx >> 4, c4 = idx & 15;
                float4 a0 = sE[(0*32 + qi)*17 + c4];
                float4 a1 = sE[(1*32 + qi)*17 + c4];
                float4 a2 = sE[(2*32 + qi)*17 + c4];
                float4 a3 = sE[(3*32 + qi)*17 + c4];
                float l0 = sLinv[qi], l1 = sLinv[32+qi], l2 = sLinv[64+qi], l3 = sLinv[96+qi];
                float4 r;
                r.x = 0.25f*(a0.x*l0 + a1.x*l1 + a2.x*l2 + a3.x*l3);
                r.y = 0.25f*(a0.y*l0 + a1.y*l1 + a2.y*l2 + a3.y*l3);
                r.z = 0.25f*(a0.z*l0 + a1.z*l1 + a2.z*l2 + a3.z*l3);
                r.w = 0.25f*(a0.w*l0 + a1.w*l1 + a2.w*l2 + a3.w*l3);
                reinterpret_cast<float4*>(om + (size_t)(b*S + q0 + qi)*S + j0 + 4*c4)[0] = r;
            }
        }

        // O accumulation
        #pragma unroll 4
        for (int jt = 0; jt < TK; jt += 4) {
            const int jc = jt >> 2;
            float4 e0 = sE[ebase0 + jc];
            float4 e1 = sE[ebase1 + jc];
            #pragma unroll
            for (int jj = 0; jj < 4; jj++) {
                const int j = jt + jj;
                const int sw = (j >> 2) & 7;
                float4 v0 = sV[j*48 + ((c0+0) ^ sw)];
                float4 v1 = sV[j*48 + ((c0+1) ^ sw)];
                float4 v2 = sV[j*48 + ((c0+2) ^ sw)];
                float ea = (jj==0) ? e0.x : (jj==1) ? e0.y : (jj==2) ? e0.z : e0.w;
                float eb = (jj==0) ? e1.x : (jj==1) ? e1.y : (jj==2) ? e1.z : e1.w;
                unsigned long long ea2 = pack2(ea, ea), eb2 = pack2(eb, eb);
                const unsigned long long* p0 = reinterpret_cast<const unsigned long long*>(&v0);
                const unsigned long long* p1 = reinterpret_cast<const unsigned long long*>(&v1);
                const unsigned long long* p2 = reinterpret_cast<const unsigned long long*>(&v2);
                ffma2(oacc[0][0], ea2, p0[0]); ffma2(oacc[0][1], ea2, p0[1]);
                ffma2(oacc[0][2], ea2, p1[0]); ffma2(oacc[0][3], ea2, p1[1]);
                ffma2(oacc[0][4], ea2, p2[0]); ffma2(oacc[0][5], ea2, p2[1]);
                ffma2(oacc[1][0], eb2, p0[0]); ffma2(oacc[1][1], eb2, p0[1]);
                ffma2(oacc[1][2], eb2, p1[0]); ffma2(oacc[1][3], eb2, p1[1]);
                ffma2(oacc[1][4], eb2, p2[0]); ffma2(oacc[1][5], eb2, p2[1]);
            }
        }
    }

    // finalize: scale by Linv, write ctx
    #pragma unroll
    for (int u = 0; u < 2; u++) {
        const int qi = 2*qg + u;
        const float linv = sLinv[h*32 + qi];
        float4* dst = reinterpret_cast<float4*>(g_ctx + (size_t)(b*S + q0 + qi)*D + h*48 + pg*12);
        #pragma unroll
        for (int m = 0; m < 3; m++) {
            float x0, y0, x1, y1;
            unpack2(oacc[u][2*m+0], x0, y0);
            unpack2(oacc[u][2*m+1], x1, y1);
            float4 o; o.x = x0*linv; o.y = y0*linv; o.z = x1*linv; o.w = y1*linv;
            dst[m] = o;
        }
    }
}

extern "C" void kernel_launch(void* const* d_in, const int* in_sizes, int n_in,
                              void* d_out, int out_size) {
    (void)in_sizes; (void)n_in; (void)out_size;
    const float* query = (const float*)d_in[0];
    const float* key   = (const float*)d_in[1];
    const float* value = (const float*)d_in[2];
    const int*   mask  = (const int*)  d_in[3];
    const float* bias  = (const float*)d_in[4];
    const float* Wq    = (const float*)d_in[5];
    const float* Wk    = (const float*)d_in[6];
    const float* Wv    = (const float*)d_in[7];
    const float* Wo    = (const float*)d_in[8];

    float* out = (float*)d_out;                 // [B,S,D]
    float* om  = out + B*S*D;                   // [B,S,S] mean weights

    float *pq, *pk, *pv, *pctx;
    cudaGetSymbolAddress((void**)&pq,   g_q);
    cudaGetSymbolAddress((void**)&pk,   g_k);
    cudaGetSymbolAddress((void**)&pv,   g_v);
    cudaGetSymbolAddress((void**)&pctx, g_ctx);

    cudaFuncSetAttribute(proj_kernel,   cudaFuncAttributeMaxDynamicSharedMemorySize, PROJ_SMEM);
    cudaFuncSetAttribute(logits_kernel, cudaFuncAttributeMaxDynamicSharedMemorySize, A_SMEM);
    cudaFuncSetAttribute(pv_kernel,     cudaFuncAttributeMaxDynamicSharedMemorySize, B_SMEM);

    proj_kernel<<<256, 256, PROJ_SMEM>>>(query, Wq, pq);
    proj_kernel<<<256, 256, PROJ_SMEM>>>(key,   Wk, pk);
    proj_kernel<<<256, 256, PROJ_SMEM>>>(value, Wv, pv);
    logits_kernel<<<dim3(B, S/TQ), 256, A_SMEM>>>(mask, bias);
    pv_kernel<<<dim3(B, S/TQ), 256, B_SMEM>>>(om);
    proj_kernel<<<256, 256, PROJ_SMEM>>>(pctx, Wo, out);
}

// round 3
// speedup vs baseline: 1.6737x; 1.0773x over previous
#include <cuda_runtime.h>
#include <cstdint>

#define B 4
#define S 2048
#define H 4
#define DH 48
#define D 192
#define TQ 64
#define TK 64
#define NT (S/TK)
#define NEG_INF -1000000000.0f

// Scratch
__device__ float g_q[B*S*D];
__device__ float g_k[B*S*D];
__device__ float g_v[B*S*D];
__device__ float g_ctx[B*S*D];
__device__ float g_E[(size_t)B*H*S*S];   // 256MB unnormalized exp(logits)
__device__ float g_Linv[B*H*S];
__device__ float g_WT[4][D*D];           // pre-transposed weights [k][j]

// ---------- packed fp32x2 helpers ----------
__device__ __forceinline__ unsigned long long pack2(float x, float y) {
    unsigned long long r;
    asm("mov.b64 %0, {%1,%2};" : "=l"(r) : "f"(x), "f"(y));
    return r;
}
__device__ __forceinline__ void unpack2(unsigned long long v, float& x, float& y) {
    asm("mov.b64 {%0,%1}, %2;" : "=f"(x), "=f"(y) : "l"(v));
}
__device__ __forceinline__ void ffma2(unsigned long long& d, unsigned long long a, unsigned long long b) {
    asm("fma.rn.f32x2 %0, %1, %2, %0;" : "+l"(d) : "l"(a), "l"(b));
}

// ---------- cp.async helpers ----------
__device__ __forceinline__ void cp16(uint32_t saddr, const void* gptr) {
    asm volatile("cp.async.cg.shared.global [%0], [%1], 16;" :: "r"(saddr), "l"(gptr));
}
__device__ __forceinline__ void cp_commit() {
    asm volatile("cp.async.commit_group;");
}
__device__ __forceinline__ void cp_wait1() {
    asm volatile("cp.async.wait_group 1;");
}
__device__ __forceinline__ void cp_wait0() {
    asm volatile("cp.async.wait_group 0;");
}
__device__ __forceinline__ uint32_t cvta_s(const void* p) {
    return (uint32_t)__cvta_generic_to_shared(p);
}

// ---------- weight transpose: WT[k][j] = W[j][k] ----------
__global__ void transpose_w(const float* __restrict__ W0, const float* __restrict__ W1,
                            const float* __restrict__ W2, const float* __restrict__ W3) {
    __shared__ float tile[32][33];
    const float* W = (blockIdx.z == 0) ? W0 : (blockIdx.z == 1) ? W1 : (blockIdx.z == 2) ? W2 : W3;
    float* WT = g_WT[blockIdx.z];
    int x = blockIdx.x*32 + threadIdx.x;
    int y = blockIdx.y*32 + threadIdx.y;
    #pragma unroll
    for (int j = 0; j < 32; j += 8)
        tile[threadIdx.y + j][threadIdx.x] = W[(y + j)*D + x];
    __syncthreads();
    int x2 = blockIdx.y*32 + threadIdx.x;
    int y2 = blockIdx.x*32 + threadIdx.y;
    #pragma unroll
    for (int j = 0; j < 32; j += 8)
        WT[(y2 + j)*D + x2] = tile[threadIdx.x][threadIdx.y + j];
}

// ---------- projection: Y[r][j] = sum_k X[r][k] * WT[k][j] ----------
// block = 32 rows x 96 cols (jh = blockIdx.y). 2 CTAs/SM.
#define PROJ_SMEM ((192*33 + 192*104)*4)
__global__ __launch_bounds__(256) void proj_kernel(const float* __restrict__ X,
                                                   const float* __restrict__ WTg,
                                                   float* __restrict__ Y) {
    extern __shared__ float sm[];
    float* sXT = sm;            // [192][33]  k-major X^T
    float* sWT = sm + 192*33;   // [192][104] k-major, 96 cols + pad
    const int tid = threadIdx.x;
    const int r0 = blockIdx.x * 32;
    const int jh = blockIdx.y;

    { // WT half: coalesced LDG.128 -> conflict-free STS.128
        const float4* src = reinterpret_cast<const float4*>(WTg);
        #pragma unroll
        for (int k = 0; k < 18; k++) {
            int idx = tid + k*256;            // 4608 float4
            int kk = idx / 24, c = idx % 24;
            reinterpret_cast<float4*>(&sWT[kk*104 + c*4])[0] = src[kk*48 + jh*24 + c];
        }
    }
    { // X transpose
        const float4* x4 = reinterpret_cast<const float4*>(X + (size_t)r0 * D);
        #pragma unroll
        for (int k = 0; k < 6; k++) {
            int idx = tid + k*256;
            int r = idx / 48, c = idx % 48;
            float4 v = x4[idx];
            sXT[(c*4+0)*33 + r] = v.x;
            sXT[(c*4+1)*33 + r] = v.y;
            sXT[(c*4+2)*33 + r] = v.z;
            sXT[(c*4+3)*33 + r] = v.w;
        }
    }
    __syncthreads();

    const int r  = tid & 31;
    const int cg = tid >> 5;   // warp-uniform -> sWT reads broadcast
    unsigned long long acc[6];
    #pragma unroll
    for (int c = 0; c < 6; c++) acc[c] = 0ull;

    #pragma unroll 4
    for (int kk = 0; kk < 192; kk++) {
        float xv = sXT[kk*33 + r];
        unsigned long long x2 = pack2(xv, xv);
        const unsigned long long* wrow =
            reinterpret_cast<const unsigned long long*>(&sWT[kk*104 + cg*12]);
        #pragma unroll
        for (int c = 0; c < 6; c++) ffma2(acc[c], x2, wrow[c]);
    }
    float* dst = Y + (size_t)(r0 + r) * D + jh*96 + cg*12;
    #pragma unroll
    for (int m = 0; m < 3; m++) {
        float x0, y0, x1, y1;
        unpack2(acc[2*m+0], x0, y0);
        unpack2(acc[2*m+1], x1, y1);
        float4 o; o.x = x0; o.y = y0; o.z = x1; o.w = y1;
        reinterpret_cast<float4*>(dst)[m] = o;
    }
}

// ============================================================================
// logits: E = exp(QK^T + bias, masked), rowsums -> g_Linv.
// Block (b, 64-q tile): 4h x 64qi x 64j. Thread: 8 qi x 8 j.
// sQ [64][48 f4] + double-buffered sK via cp.async. 1 CTA/SM, grid=128.
// ============================================================================
#define A_SMEM ((64*48 + 2*64*48)*16)
__global__ __launch_bounds__(256, 1) void logits_kernel(const int* __restrict__ gmask,
                                                        const float* __restrict__ gbias) {
    extern __shared__ float4 smA[];
    float4* sQ = smA;                 // 64*48
    float4* sK = smA + 64*48;         // 2 x 64*48
    const int tid = threadIdx.x;
    const int b  = blockIdx.x;
    const int q0 = blockIdx.y * TQ;
    const int jg = tid & 7, rg = tid >> 3;
    const int h  = rg >> 3;
    const int qi0 = (rg & 7) * 8;

    const uint32_t sQ_a = cvta_s(sQ);
    const uint32_t sK_a = cvta_s(sK);

    // prologue: Q + K(0) via cp.async, one group
    {
        const float* gq = g_q + (size_t)(b*S + q0) * D;
        const float* gk = g_k + (size_t)(b*S) * D;
        #pragma unroll
        for (int k = 0; k < 12; k++) {
            int idx = tid + k*256;
            int r = idx / 48, c = idx - r*48;
            cp16(sQ_a + (r*48 + (c ^ ((r>>2)&7)))*16, gq + (size_t)r*D + c*4);
            cp16(sK_a + (r*48 + (c ^ ((r>>2)&7)))*16, gk + (size_t)r*D + c*4);
        }
        cp_commit();
    }

    float lsum[8];
    #pragma unroll
    for (int i = 0; i < 8; i++) lsum[i] = 0.f;

    int joff[8];
    #pragma unroll
    for (int m = 0; m < 8; m++) joff[m] = (4*jg + (m&3) + 32*(m>>2)) * 48;

    for (int t = 0; t < NT; t++) {
        if (t+1 < NT) {
            const float* gk = g_k + (size_t)(b*S + (t+1)*TK) * D;
            uint32_t base = sK_a + ((t+1)&1) * 3072 * 16;
            #pragma unroll
            for (int k = 0; k < 12; k++) {
                int idx = tid + k*256;
                int r = idx / 48, c = idx - r*48;
                cp16(base + (r*48 + (c ^ ((r>>2)&7)))*16, gk + (size_t)r*D + c*4);
            }
            cp_commit();
            cp_wait1();
        } else {
            cp_wait0();
        }
        __syncthreads();
        const float4* K = sK + (t&1) * 3072;

        unsigned long long acc[8][8];
        #pragma unroll
        for (int i = 0; i < 8; i++)
            #pragma unroll
            for (int m = 0; m < 8; m++) acc[i][m] = 0ull;

        #pragma unroll
        for (int ch = 0; ch < 12; ch++) {
            const int cc = h*12 + ch;
            float4 qv[8];
            #pragma unroll
            for (int i = 0; i < 8; i++)
                qv[i] = sQ[(qi0+i)*48 + (cc ^ (((qi0+i)>>2)&7))];
            #pragma unroll
            for (int m = 0; m < 8; m++) {
                float4 kv = K[joff[m] + (cc ^ jg)];
                const unsigned long long* kp = reinterpret_cast<const unsigned long long*>(&kv);
                #pragma unroll
                for (int i = 0; i < 8; i++) {
                    const unsigned long long* qp = reinterpret_cast<const unsigned long long*>(&qv[i]);
                    ffma2(acc[i][m], qp[0], kp[0]);
                    ffma2(acc[i][m], qp[1], kp[1]);
                }
            }
        }
        __syncthreads();   // all warps done reading sK buffer before next overwrite

        // epilogue: mask/bias from gmem, exp, store E (gmem+regs only)
        const int j0 = t * TK;
        #pragma unroll
        for (int i = 0; i < 8; i++) {
            const int qi = q0 + qi0 + i;
            #pragma unroll
            for (int c = 0; c < 2; c++) {
                const int jc = j0 + 32*c + 4*jg;
                int4   mv = *reinterpret_cast<const int4*>(gmask + (size_t)(b*S + qi)*S + jc);
                float4 bv = *reinterpret_cast<const float4*>(gbias + (size_t)(h*S + qi)*S + jc);
                float4 ev;
                float ax, ay;
                unpack2(acc[i][4*c+0], ax, ay); ev.x = __expf(mv.x ? ax + ay + bv.x : NEG_INF);
                unpack2(acc[i][4*c+1], ax, ay); ev.y = __expf(mv.y ? ax + ay + bv.y : NEG_INF);
                unpack2(acc[i][4*c+2], ax, ay); ev.z = __expf(mv.z ? ax + ay + bv.z : NEG_INF);
                unpack2(acc[i][4*c+3], ax, ay); ev.w = __expf(mv.w ? ax + ay + bv.w : NEG_INF);
                lsum[i] += (ev.x + ev.y) + (ev.z + ev.w);
                *reinterpret_cast<float4*>(g_E + (size_t)((b*H + h)*S + qi)*S + jc) = ev;
            }
        }
    }

    #pragma unroll
    for (int i = 0; i < 8; i++) {
        float v = lsum[i];
        v += __shfl_xor_sync(0xffffffffu, v, 1);
        v += __shfl_xor_sync(0xffffffffu, v, 2);
        v += __shfl_xor_sync(0xffffffffu, v, 4);
        if (jg == 0) g_Linv[(b*H + h)*S + q0 + qi0 + i] = 1.0f / v;
    }
}

// ============================================================================
// pv: O = (E*Linv) @ V -> g_ctx, fused head-mean -> om.
// Block (b, 64-q tile): 4h x 64qi x 48dh. Thread: 8 qi x 6 f32x2-pairs,
// j split in halves (jh), reduced by shuffle at the end.
// sE double-buffered [2][256][68] via cp.async, sV [64][48 f4] single. 1 CTA.
// ============================================================================
#define SE_STRIDE 68
#define SE_FLOATS (256*SE_STRIDE)
#define PV_SMEM ((2*SE_FLOATS + 64*48*4 + 256)*4)
__global__ __launch_bounds__(256, 1) void pv_kernel(float* __restrict__ om) {
    extern __shared__ float smP[];
    float*  sE = smP;                          // [2][256][68]
    float4* sV = reinterpret_cast<float4*>(smP + 2*SE_FLOATS);  // 64*48
    float*  sLinv = smP + 2*SE_FLOATS + 64*48*4;                // 256
    const int tid = threadIdx.x;
    const int b  = blockIdx.x;
    const int q0 = blockIdx.y * TQ;
    const int low = tid & 63;
    const int h  = tid >> 6;
    const int qg = low >> 3;          // 8-qi octet
    const int pg = (low >> 1) & 3;    // 6-pair group
    const int jh = low & 1;           // j half
    const int rb = h*64 + qg*8;
    const int c0 = h*12 + pg*3;       // f4 column base in V

    const uint32_t sE_a = cvta_s(sE);
    const uint32_t sV_a = cvta_s(sV);

    // prologue: E(0) + V(0), one group; Linv plain load
    {
        #pragma unroll
        for (int k = 0; k < 16; k++) {
            int idx = tid + k*256;
            int row = idx >> 4, c4 = idx & 15;
            const float* src = g_E + (size_t)((b*H + (row>>6))*S + q0 + (row&63))*S + c4*4;
            cp16(sE_a + (row*SE_STRIDE + c4*4)*4, src);
        }
        const float* gv = g_v + (size_t)(b*S) * D;
        #pragma unroll
        for (int k = 0; k < 12; k++) {
            int idx = tid + k*256;
            int r = idx / 48, c = idx - r*48;
            cp16(sV_a + (r*48 + (c ^ ((r>>2)&7)))*16, gv + (size_t)r*D + c*4);
        }
        cp_commit();
        sLinv[tid] = g_Linv[(b*H + (tid>>6))*S + q0 + (tid & 63)];
    }

    unsigned long long acc[8][6];
    #pragma unroll
    for (int i = 0; i < 8; i++)
        #pragma unroll
        for (int p = 0; p < 6; p++) acc[i][p] = 0ull;

    for (int t = 0; t < NT; t++) {
        if (t+1 < NT) { // prefetch E(t+1) into other buffer
            uint32_t base = sE_a + ((t+1)&1) * SE_FLOATS * 4;
            #pragma unroll
            for (int k = 0; k < 16; k++) {
                int idx = tid + k*256;
                int row = idx >> 4, c4 = idx & 15;
                const float* src = g_E + (size_t)((b*H + (row>>6))*S + q0 + (row&63))*S + (t+1)*TK + c4*4;
                cp16(base + (row*SE_STRIDE + c4*4)*4, src);
            }
            cp_commit();
            cp_wait1();
        } else {
            cp_wait0();
        }
        __syncthreads();
        const float* E = sE + (t&1) * SE_FLOATS;

        { // head-mean output tile (coalesced write)
            #pragma unroll
            for (int k = 0; k < 4; k++) {
                int idx = tid + k*256;
                int qi = idx >> 4, c4 = idx & 15;
                float4 a0 = *reinterpret_cast<const float4*>(&E[(0*64 + qi)*SE_STRIDE + c4*4]);
                float4 a1 = *reinterpret_cast<const float4*>(&E[(1*64 + qi)*SE_STRIDE + c4*4]);
                float4 a2 = *reinterpret_cast<const float4*>(&E[(2*64 + qi)*SE_STRIDE + c4*4]);
                float4 a3 = *reinterpret_cast<const float4*>(&E[(3*64 + qi)*SE_STRIDE + c4*4]);
                float l0 = sLinv[qi], l1 = sLinv[64+qi], l2 = sLinv[128+qi], l3 = sLinv[192+qi];
                float4 r;
                r.x = 0.25f*(a0.x*l0 + a1.x*l1 + a2.x*l2 + a3.x*l3);
                r.y = 0.25f*(a0.y*l0 + a1.y*l1 + a2.y*l2 + a3.y*l3);
                r.z = 0.25f*(a0.z*l0 + a1.z*l1 + a2.z*l2 + a3.z*l3);
                r.w = 0.25f*(a0.w*l0 + a1.w*l1 + a2.w*l2 + a3.w*l3);
                *reinterpret_cast<float4*>(om + (size_t)(b*S + q0 + qi)*S + t*TK + 4*c4) = r;
            }
        }

        // PV accumulation over this thread's j half
        #pragma unroll 2
        for (int jj = 0; jj < 32; jj++) {
            const int j = jh*32 + jj;
            const int sw = (j >> 2) & 7;
            unsigned long long e2[8];
            #pragma unroll
            for (int i = 0; i < 8; i++) {
                float e = E[(rb + i)*SE_STRIDE + j];
                e2[i] = pack2(e, e);
            }
            float4 v0 = sV[j*48 + ((c0+0) ^ sw)];
            float4 v1 = sV[j*48 + ((c0+1) ^ sw)];
            float4 v2 = sV[j*48 + ((c0+2) ^ sw)];
            const unsigned long long* p0 = reinterpret_cast<const unsigned long long*>(&v0);
            const unsigned long long* p1 = reinterpret_cast<const unsigned long long*>(&v1);
            const unsigned long long* p2 = reinterpret_cast<const unsigned long long*>(&v2);
            #pragma unroll
            for (int i = 0; i < 8; i++) {
                ffma2(acc[i][0], e2[i], p0[0]); ffma2(acc[i][1], e2[i], p0[1]);
                ffma2(acc[i][2], e2[i], p1[0]); ffma2(acc[i][3], e2[i], p1[1]);
                ffma2(acc[i][4], e2[i], p2[0]); ffma2(acc[i][5], e2[i], p2[1]);
            }
        }
        __syncthreads();   // everyone done with sV + sE(t&1)

        if (t+1 < NT) { // refill V (single buffer, now free)
            const float* gv = g_v + (size_t)(b*S + (t+1)*TK) * D;
            #pragma unroll
            for (int k = 0; k < 12; k++) {
                int idx = tid + k*256;
                int r = idx / 48, c = idx - r*48;
                cp16(sV_a + (r*48 + (c ^ ((r>>2)&7)))*16, gv + (size_t)r*D + c*4);
            }
            cp_commit();
        }
    }

    // reduce over jh pairs (adjacent lanes), scale, store ctx
    #pragma unroll
    for (int i = 0; i < 8; i++) {
        const int qi = qg*8 + i;
        const float linv = sLinv[h*64 + qi];
        float xs[6], ys[6];
        #pragma unroll
        for (int p = 0; p < 6; p++) {
            float x, y; unpack2(acc[i][p], x, y);
            x += __shfl_xor_sync(0xffffffffu, x, 1);
            y += __shfl_xor_sync(0xffffffffu, y, 1);
            xs[p] = x * linv; ys[p] = y * linv;
        }
        if (jh == 0) {
            float4* dst = reinterpret_cast<float4*>(g_ctx + (size_t)(b*S + q0 + qi)*D + h*48 + pg*12);
            #pragma unroll
            for (int m = 0; m < 3; m++) {
                float4 o; o.x = xs[2*m]; o.y = ys[2*m]; o.z = xs[2*m+1]; o.w = ys[2*m+1];
                dst[m] = o;
            }
        }
    }
}

extern "C" void kernel_launch(void* const* d_in, const int* in_sizes, int n_in,
                              void* d_out, int out_size) {
    (void)in_sizes; (void)n_in; (void)out_size;
    const float* query = (const float*)d_in[0];
    const float* key   = (const float*)d_in[1];
    const float* value = (const float*)d_in[2];
    const int*   mask  = (const int*)  d_in[3];
    const float* bias  = (const float*)d_in[4];
    const float* Wq    = (const float*)d_in[5];
    const float* Wk    = (const float*)d_in[6];
    const float* Wv    = (const float*)d_in[7];
    const float* Wo    = (const float*)d_in[8];

    float* out = (float*)d_out;                 // [B,S,D]
    float* om  = out + B*S*D;                   // [B,S,S] mean weights

    float *pq, *pk, *pv, *pctx, *pwt;
    cudaGetSymbolAddress((void**)&pq,   g_q);
    cudaGetSymbolAddress((void**)&pk,   g_k);
    cudaGetSymbolAddress((void**)&pv,   g_v);
    cudaGetSymbolAddress((void**)&pctx, g_ctx);
    cudaGetSymbolAddress((void**)&pwt,  g_WT);

    cudaFuncSetAttribute(proj_kernel,   cudaFuncAttributeMaxDynamicSharedMemorySize, PROJ_SMEM);
    cudaFuncSetAttribute(logits_kernel, cudaFuncAttributeMaxDynamicSharedMemorySize, A_SMEM);
    cudaFuncSetAttribute(pv_kernel,     cudaFuncAttributeMaxDynamicSharedMemorySize, PV_SMEM);

    transpose_w<<<dim3(6,6,4), dim3(32,8)>>>(Wq, Wk, Wv, Wo);
    proj_kernel<<<dim3(256,2), 256, PROJ_SMEM>>>(query, pwt + 0*D*D, pq);
    proj_kernel<<<dim3(256,2), 256, PROJ_SMEM>>>(key,   pwt + 1*D*D, pk);
    proj_kernel<<<dim3(256,2), 256, PROJ_SMEM>>>(value, pwt + 2*D*D, pv);
    logits_kernel<<<dim3(B, S/TQ), 256, A_SMEM>>>(mask, bias);
    pv_kernel<<<dim3(B, S/TQ), 256, PV_SMEM>>>(om);
    proj_kernel<<<dim3(256,2), 256, PROJ_SMEM>>>(pctx, pwt + 3*D*D, out);
}

// round 4
// speedup vs baseline: 1.9925x; 1.1905x over previous
#include <cuda_runtime.h>
#include <cstdint>

#define B 4
#define S 2048
#define H 4
#define DH 48
#define D 192
#define TQ 32
#define TK 64
#define NT (S/TK)
#define TKV 32
#define NT2 (S/TKV)
#define NEG_INF -1000000000.0f

// Scratch
__device__ float g_q[B*S*D];
__device__ float g_k[B*S*D];
__device__ float g_v[B*S*D];
__device__ float g_ctx[B*S*D];
__device__ float g_E[(size_t)B*H*S*S];   // 256MB unnormalized exp(logits)
__device__ float g_Linv[B*H*S];
__device__ float g_WT[4][D*D];           // pre-transposed weights [k][j]

// ---------- packed fp32x2 helpers ----------
__device__ __forceinline__ unsigned long long pack2(float x, float y) {
    unsigned long long r;
    asm("mov.b64 %0, {%1,%2};" : "=l"(r) : "f"(x), "f"(y));
    return r;
}
__device__ __forceinline__ void unpack2(unsigned long long v, float& x, float& y) {
    asm("mov.b64 {%0,%1}, %2;" : "=f"(x), "=f"(y) : "l"(v));
}
__device__ __forceinline__ void ffma2(unsigned long long& d, unsigned long long a, unsigned long long b) {
    asm("fma.rn.f32x2 %0, %1, %2, %0;" : "+l"(d) : "l"(a), "l"(b));
}

// ---------- cp.async helpers ----------
__device__ __forceinline__ void cp16(uint32_t saddr, const void* gptr) {
    asm volatile("cp.async.cg.shared.global [%0], [%1], 16;" :: "r"(saddr), "l"(gptr));
}
__device__ __forceinline__ void cp_commit() { asm volatile("cp.async.commit_group;"); }
__device__ __forceinline__ void cp_wait1()  { asm volatile("cp.async.wait_group 1;"); }
__device__ __forceinline__ void cp_wait0()  { asm volatile("cp.async.wait_group 0;"); }
__device__ __forceinline__ uint32_t cvta_s(const void* p) {
    return (uint32_t)__cvta_generic_to_shared(p);
}

// swizzles
__device__ __forceinline__ int swzE(int row) { return ((row>>3) ^ (row>>5)) & 7; }
__device__ __forceinline__ int swzV(int r)   { return ((r>>2)&7) ^ ((r&1)<<2); }

// ---------- weight transpose: WT[k][j] = W[j][k] ----------
__global__ void transpose_w(const float* __restrict__ W0, const float* __restrict__ W1,
                            const float* __restrict__ W2, const float* __restrict__ W3) {
    __shared__ float tile[32][33];
    const float* W = (blockIdx.z == 0) ? W0 : (blockIdx.z == 1) ? W1 : (blockIdx.z == 2) ? W2 : W3;
    float* WT = g_WT[blockIdx.z];
    int x = blockIdx.x*32 + threadIdx.x;
    int y = blockIdx.y*32 + threadIdx.y;
    #pragma unroll
    for (int j = 0; j < 32; j += 8)
        tile[threadIdx.y + j][threadIdx.x] = W[(y + j)*D + x];
    __syncthreads();
    int x2 = blockIdx.y*32 + threadIdx.x;
    int y2 = blockIdx.x*32 + threadIdx.y;
    #pragma unroll
    for (int j = 0; j < 32; j += 8)
        WT[(y2 + j)*D + x2] = tile[threadIdx.x][threadIdx.y + j];
}

// ---------- projection core: Y[r][j] = sum_k X[r][k] * WT[k][j] ----------
// 32 rows/block, full 192 cols. 128 threads: warp->8 rows, lane->6 cols.
// W streamed from gmem through L1 (147KB WT set stays hot). X^T in smem.
__device__ __forceinline__ void proj_core(const float* __restrict__ X,
                                          const float* __restrict__ WT,
                                          float* __restrict__ Y, int r0) {
    __shared__ float sXT[192*33];
    const int tid = threadIdx.x;
    const int w = tid >> 5, lane = tid & 31;

    #pragma unroll
    for (int k = 0; k < 12; k++) {
        int idx = tid + k*128;                 // 1536 float4
        int r = idx / 48, c = idx % 48;
        float4 v = *reinterpret_cast<const float4*>(X + (size_t)(r0 + r)*D + 4*c);
        sXT[(4*c+0)*33 + r] = v.x;
        sXT[(4*c+1)*33 + r] = v.y;
        sXT[(4*c+2)*33 + r] = v.z;
        sXT[(4*c+3)*33 + r] = v.w;
    }
    __syncthreads();

    unsigned long long acc[8][3];
    #pragma unroll
    for (int i = 0; i < 8; i++)
        #pragma unroll
        for (int p = 0; p < 3; p++) acc[i][p] = 0ull;

    #pragma unroll 2
    for (int k = 0; k < 192; k++) {
        const unsigned long long* wrow =
            reinterpret_cast<const unsigned long long*>(WT + k*D + lane*6);
        unsigned long long w0 = wrow[0], w1 = wrow[1], w2 = wrow[2];
        #pragma unroll
        for (int i = 0; i < 8; i++) {
            float xv = sXT[k*33 + w*8 + i];    // warp-broadcast
            unsigned long long x2 = pack2(xv, xv);
            ffma2(acc[i][0], x2, w0);
            ffma2(acc[i][1], x2, w1);
            ffma2(acc[i][2], x2, w2);
        }
    }
    #pragma unroll
    for (int i = 0; i < 8; i++) {
        unsigned long long* dst =
            reinterpret_cast<unsigned long long*>(Y + (size_t)(r0 + w*8 + i)*D + lane*6);
        dst[0] = acc[i][0]; dst[1] = acc[i][1]; dst[2] = acc[i][2];
    }
}

__global__ __launch_bounds__(128, 4) void proj3_kernel(const float* __restrict__ X0,
                                                       const float* __restrict__ X1,
                                                       const float* __restrict__ X2,
                                                       float* __restrict__ Y0,
                                                       float* __restrict__ Y1,
                                                       float* __restrict__ Y2) {
    const int which = blockIdx.y;
    const float* X = (which == 0) ? X0 : (which == 1) ? X1 : X2;
    float*       Y = (which == 0) ? Y0 : (which == 1) ? Y1 : Y2;
    proj_core(X, g_WT[which], Y, blockIdx.x * 32);
}

__global__ __launch_bounds__(128, 4) void proj1_kernel(const float* __restrict__ X,
                                                       float* __restrict__ Y) {
    proj_core(X, g_WT[3], Y, blockIdx.x * 32);
}

// ============================================================================
// logits: E = exp(QK^T + bias, masked), 1/rowsum -> g_Linv.
// Grid (B, S/32) = 256 blocks, 256 threads, 2 CTAs/SM (<=128 regs).
// Thread: h = (tid>>4)>>2, qg = (tid>>4)&3 -> 8 qi; jg = tid&15 -> 4 j.
// sQ [32][48 f4] + sK [64][48 f4] single buffer; K(t+1) cp.async overlaps
// the gmem epilogue of tile t.
// ============================================================================
#define A_SMEM ((32*48 + 64*48)*16)
__global__ __launch_bounds__(256, 2) void logits_kernel(const int* __restrict__ gmask,
                                                        const float* __restrict__ gbias) {
    extern __shared__ float4 smA[];
    float4* sQ = smA;             // 32*48
    float4* sK = smA + 32*48;     // 64*48
    const int tid = threadIdx.x;
    const int b  = blockIdx.x;
    const int q0 = blockIdx.y * TQ;
    const int jg = tid & 15, rg = tid >> 4;
    const int h  = rg >> 2;
    const int qi0 = (rg & 3) * 8;

    const uint32_t sQ_a = cvta_s(sQ);
    const uint32_t sK_a = cvta_s(sK);

    { // prologue: Q + K(0)
        const float* gq = g_q + (size_t)(b*S + q0) * D;
        const float* gk = g_k + (size_t)(b*S) * D;
        #pragma unroll
        for (int k = 0; k < 6; k++) {
            int idx = tid + k*256;            // 1536
            int r = idx / 48, c = idx - r*48;
            cp16(sQ_a + (r*48 + (c ^ ((r>>2)&7)))*16, gq + (size_t)r*D + c*4);
        }
        #pragma unroll
        for (int k = 0; k < 12; k++) {
            int idx = tid + k*256;            // 3072
            int r = idx / 48, c = idx - r*48;
            cp16(sK_a + (r*48 + (c ^ ((r>>2)&7)))*16, gk + (size_t)r*D + c*4);
        }
        cp_commit();
    }

    float lsum[8];
    #pragma unroll
    for (int i = 0; i < 8; i++) lsum[i] = 0.f;

    for (int t = 0; t < NT; t++) {
        cp_wait0();
        __syncthreads();

        unsigned long long acc[8][4];
        #pragma unroll
        for (int i = 0; i < 8; i++)
            #pragma unroll
            for (int m = 0; m < 4; m++) acc[i][m] = 0ull;

        #pragma unroll
        for (int ch = 0; ch < 12; ch++) {
            const int cc = h*12 + ch;
            float4 qv[8];
            #pragma unroll
            for (int i = 0; i < 8; i++)
                qv[i] = sQ[(qi0+i)*48 + (cc ^ (((qi0+i)>>2)&7))];   // broadcast
            #pragma unroll
            for (int m = 0; m < 4; m++) {
                const int r = 4*jg + m;
                float4 kv = sK[r*48 + (cc ^ ((r>>2)&7))];            // conflict-free
                const unsigned long long* kp = reinterpret_cast<const unsigned long long*>(&kv);
                #pragma unroll
                for (int i = 0; i < 8; i++) {
                    const unsigned long long* qp = reinterpret_cast<const unsigned long long*>(&qv[i]);
                    ffma2(acc[i][m], qp[0], kp[0]);
                    ffma2(acc[i][m], qp[1], kp[1]);
                }
            }
        }
        __syncthreads();

        if (t+1 < NT) { // prefetch K(t+1); overlaps the gmem epilogue below
            const float* gk = g_k + (size_t)(b*S + (t+1)*TK) * D;
            #pragma unroll
            for (int k = 0; k < 12; k++) {
                int idx = tid + k*256;
                int r = idx / 48, c = idx - r*48;
                cp16(sK_a + (r*48 + (c ^ ((r>>2)&7)))*16, gk + (size_t)r*D + c*4);
            }
            cp_commit();
        }

        // epilogue: mask/bias from gmem, exp, store E
        const int jc = t*TK + 4*jg;
        #pragma unroll
        for (int i = 0; i < 8; i++) {
            const int qi = q0 + qi0 + i;
            int4   mv = *reinterpret_cast<const int4*>(gmask + (size_t)(b*S + qi)*S + jc);
            float4 bv = *reinterpret_cast<const float4*>(gbias + (size_t)(h*S + qi)*S + jc);
            float4 ev;
            float ax, ay;
            unpack2(acc[i][0], ax, ay); ev.x = __expf(mv.x ? ax + ay + bv.x : NEG_INF);
            unpack2(acc[i][1], ax, ay); ev.y = __expf(mv.y ? ax + ay + bv.y : NEG_INF);
            unpack2(acc[i][2], ax, ay); ev.z = __expf(mv.z ? ax + ay + bv.z : NEG_INF);
            unpack2(acc[i][3], ax, ay); ev.w = __expf(mv.w ? ax + ay + bv.w : NEG_INF);
            lsum[i] += (ev.x + ev.y) + (ev.z + ev.w);
            *reinterpret_cast<float4*>(g_E + (size_t)((b*H + h)*S + qi)*S + jc) = ev;
        }
    }

    // reduce rowsums across the 16 jg lanes (lane bits 0..3)
    #pragma unroll
    for (int i = 0; i < 8; i++) {
        float v = lsum[i];
        v += __shfl_xor_sync(0xffffffffu, v, 1);
        v += __shfl_xor_sync(0xffffffffu, v, 2);
        v += __shfl_xor_sync(0xffffffffu, v, 4);
        v += __shfl_xor_sync(0xffffffffu, v, 8);
        if (jg == 0) g_Linv[(b*H + h)*S + q0 + qi0 + i] = 1.0f / v;
    }
}

// ============================================================================
// pv: O = (E*Linv) @ V -> g_ctx, fused head-mean -> om.
// Grid (B, S/32) = 256 blocks, 128 threads. Thread: h = tid>>5,
// qg = (tid>>3)&3 (8 qi), pg = (tid>>1)&3 (3 f4 cols), jh = tid&1
// (j = 2jj+jh interleave, shuffle-reduced at the end).
// sE[2][128][32] (col-f4 XOR swizzle by row), sV[2][32][48 f4] (row swizzle),
// both double-buffered in ONE cp.async group per tile.
// ============================================================================
#define PV_SMEM (2*128*32*4 + 2*32*48*16 + 128*4)
__global__ __launch_bounds__(128, 2) void pv_kernel(float* __restrict__ om) {
    extern __shared__ float smP[];
    float*  sE = smP;                                    // 2 x 4096 floats
    float4* sV = reinterpret_cast<float4*>(smP + 8192);  // 2 x 1536 f4
    float*  sLinv = smP + 8192 + 12288;                  // 128
    const int tid = threadIdx.x;
    const int b  = blockIdx.x;
    const int q0 = blockIdx.y * TQ;
    const int h  = tid >> 5;
    const int qg = (tid >> 3) & 3;
    const int pg = (tid >> 1) & 3;
    const int jh = tid & 1;
    const int rb = h*32 + qg*8;
    const int c0 = h*12 + pg*3;

    const uint32_t sE_a = cvta_s(sE);
    const uint32_t sV_a = cvta_s(sV);

    { // prologue: E(0) + V(0)
        #pragma unroll
        for (int k = 0; k < 8; k++) {
            int idx = tid + k*128;            // 1024 f4
            int row = idx >> 3, c4 = idx & 7;
            const float* src = g_E + (size_t)((b*H + (row>>5))*S + q0 + (row&31))*S + c4*4;
            cp16(sE_a + (row*32 + ((c4 ^ swzE(row))<<2))*4, src);
        }
        #pragma unroll
        for (int k = 0; k < 12; k++) {
            int idx = tid + k*128;            // 1536 f4
            int r = idx / 48, c = idx - r*48;
            cp16(sV_a + (r*48 + (c ^ swzV(r)))*16, g_v + (size_t)(b*S + r)*D + c*4);
        }
        cp_commit();
        sLinv[tid] = g_Linv[(b*H + (tid>>5))*S + q0 + (tid & 31)];
    }

    int ebase[8], eswz[8];
    #pragma unroll
    for (int i = 0; i < 8; i++) { ebase[i] = (rb+i)*32; eswz[i] = swzE(rb+i); }

    unsigned long long acc[8][6];
    #pragma unroll
    for (int i = 0; i < 8; i++)
        #pragma unroll
        for (int p = 0; p < 6; p++) acc[i][p] = 0ull;

    for (int t = 0; t < NT2; t++) {
        if (t+1 < NT2) { // prefetch E(t+1)+V(t+1) into other buffers
            const int bo = ((t+1)&1);
            #pragma unroll
            for (int k = 0; k < 8; k++) {
                int idx = tid + k*128;
                int row = idx >> 3, c4 = idx & 7;
                const float* src = g_E + (size_t)((b*H + (row>>5))*S + q0 + (row&31))*S + (t+1)*TKV + c4*4;
                cp16(sE_a + (bo*4096 + row*32 + ((c4 ^ swzE(row))<<2))*4, src);
            }
            #pragma unroll
            for (int k = 0; k < 12; k++) {
                int idx = tid + k*128;
                int r = idx / 48, c = idx - r*48;
                cp16(sV_a + (bo*1536 + r*48 + (c ^ swzV(r)))*16,
                     g_v + (size_t)(b*S + (t+1)*TKV + r)*D + c*4);
            }
            cp_commit();
            cp_wait1();
        } else {
            cp_wait0();
        }
        __syncthreads();
        const float*  Et = sE + (t&1)*4096;
        const float4* Vt = sV + (t&1)*1536;

        { // head-mean output tile
            #pragma unroll
            for (int k = 0; k < 2; k++) {
                int idx = tid + k*128;
                int c4 = idx & 7, qi = idx >> 3;
                float4 a0 = *reinterpret_cast<const float4*>(&Et[(0*32+qi)*32 + ((c4 ^ swzE(0*32+qi))<<2)]);
                float4 a1 = *reinterpret_cast<const float4*>(&Et[(1*32+qi)*32 + ((c4 ^ swzE(1*32+qi))<<2)]);
                float4 a2 = *reinterpret_cast<const float4*>(&Et[(2*32+qi)*32 + ((c4 ^ swzE(2*32+qi))<<2)]);
                float4 a3 = *reinterpret_cast<const float4*>(&Et[(3*32+qi)*32 + ((c4 ^ swzE(3*32+qi))<<2)]);
                float l0 = sLinv[qi], l1 = sLinv[32+qi], l2 = sLinv[64+qi], l3 = sLinv[96+qi];
                float4 r;
                r.x = 0.25f*(a0.x*l0 + a1.x*l1 + a2.x*l2 + a3.x*l3);
                r.y = 0.25f*(a0.y*l0 + a1.y*l1 + a2.y*l2 + a3.y*l3);
                r.z = 0.25f*(a0.z*l0 + a1.z*l1 + a2.z*l2 + a3.z*l3);
                r.w = 0.25f*(a0.w*l0 + a1.w*l1 + a2.w*l2 + a3.w*l3);
                *reinterpret_cast<float4*>(om + (size_t)(b*S + q0 + qi)*S + t*TKV + c4*4) = r;
            }
        }

        // PV accumulation: j = 2jj + jh
        #pragma unroll 4
        for (int jj = 0; jj < 16; jj++) {
            const int j = 2*jj + jh;
            const int c4j = j >> 2, lo = j & 3;
            const int swv = swzV(j);
            unsigned long long e2[8];
            #pragma unroll
            for (int i = 0; i < 8; i++) {
                float e = Et[ebase[i] + ((c4j ^ eswz[i])<<2) + lo];  // conflict-free
                e2[i] = pack2(e, e);
            }
            float4 v0 = Vt[j*48 + ((c0+0) ^ swv)];
            float4 v1 = Vt[j*48 + ((c0+1) ^ swv)];
            float4 v2 = Vt[j*48 + ((c0+2) ^ swv)];
            const unsigned long long* p0 = reinterpret_cast<const unsigned long long*>(&v0);
            const unsigned long long* p1 = reinterpret_cast<const unsigned long long*>(&v1);
            const unsigned long long* p2 = reinterpret_cast<const unsigned long long*>(&v2);
            #pragma unroll
            for (int i = 0; i < 8; i++) {
                ffma2(acc[i][0], e2[i], p0[0]); ffma2(acc[i][1], e2[i], p0[1]);
                ffma2(acc[i][2], e2[i], p1[0]); ffma2(acc[i][3], e2[i], p1[1]);
                ffma2(acc[i][4], e2[i], p2[0]); ffma2(acc[i][5], e2[i], p2[1]);
            }
        }
        __syncthreads();   // protect buffers before next-iter prefetch overwrite
    }

    // reduce jh pairs (adjacent lanes), scale, store ctx
    #pragma unroll
    for (int i = 0; i < 8; i++) {
        const int qrow = qg*8 + i;
        const float linv = sLinv[h*32 + qrow];
        float xs[6], ys[6];
        #pragma unroll
        for (int p = 0; p < 6; p++) {
            float x, y; unpack2(acc[i][p], x, y);
            x += __shfl_xor_sync(0xffffffffu, x, 1);
            y += __shfl_xor_sync(0xffffffffu, y, 1);
            xs[p] = x * linv; ys[p] = y * linv;
        }
        if (jh == 0) {
            float4* dst = reinterpret_cast<float4*>(g_ctx + (size_t)(b*S + q0 + qrow)*D + h*48 + pg*12);
            #pragma unroll
            for (int m = 0; m < 3; m++) {
                float4 o; o.x = xs[2*m]; o.y = ys[2*m]; o.z = xs[2*m+1]; o.w = ys[2*m+1];
                dst[m] = o;
            }
        }
    }
}

extern "C" void kernel_launch(void* const* d_in, const int* in_sizes, int n_in,
                              void* d_out, int out_size) {
    (void)in_sizes; (void)n_in; (void)out_size;
    const float* query = (const float*)d_in[0];
    const float* key   = (const float*)d_in[1];
    const float* value = (const float*)d_in[2];
    const int*   mask  = (const int*)  d_in[3];
    const float* bias  = (const float*)d_in[4];
    const float* Wq    = (const float*)d_in[5];
    const float* Wk    = (const float*)d_in[6];
    const float* Wv    = (const float*)d_in[7];
    const float* Wo    = (const float*)d_in[8];

    float* out = (float*)d_out;                 // [B,S,D]
    float* om  = out + B*S*D;                   // [B,S,S] mean weights

    float *pq, *pk, *pv, *pctx;
    cudaGetSymbolAddress((void**)&pq,   g_q);
    cudaGetSymbolAddress((void**)&pk,   g_k);
    cudaGetSymbolAddress((void**)&pv,   g_v);
    cudaGetSymbolAddress((void**)&pctx, g_ctx);

    cudaFuncSetAttribute(logits_kernel, cudaFuncAttributeMaxDynamicSharedMemorySize, A_SMEM);
    cudaFuncSetAttribute(pv_kernel,     cudaFuncAttributeMaxDynamicSharedMemorySize, PV_SMEM);

    transpose_w<<<dim3(6,6,4), dim3(32,8)>>>(Wq, Wk, Wv, Wo);
    proj3_kernel<<<dim3(256,3), 128>>>(query, key, value, pq, pk, pv);
    logits_kernel<<<dim3(B, S/TQ), 256, A_SMEM>>>(mask, bias);
    pv_kernel<<<dim3(B, S/TQ), 128, PV_SMEM>>>(om);
    proj1_kernel<<<dim3(256,1), 128>>>(pctx, out);
}

// round 5
// speedup vs baseline: 2.0501x; 1.0289x over previous
#include <cuda_runtime.h>
#include <cstdint>

#define B 4
#define S 2048
#define H 4
#define DH 48
#define D 192
#define TQ 32
#define TK 64
#define NT (S/TK)
#define TKV 32
#define NT2 (S/TKV)
#define NEG_INF -1000000000.0f

// Scratch
__device__ float g_q[B*S*D];
__device__ float g_k[B*S*D];
__device__ float g_v[B*S*D];
__device__ float g_ctx[B*S*D];
__device__ float g_E[(size_t)B*H*S*S];   // 256MB unnormalized exp(logits)
__device__ float g_Linv[B*H*S];
__device__ float g_WT[4][D*D];           // pre-transposed weights [k][j]

// ---------- packed fp32x2 helpers ----------
__device__ __forceinline__ unsigned long long pack2(float x, float y) {
    unsigned long long r;
    asm("mov.b64 %0, {%1,%2};" : "=l"(r) : "f"(x), "f"(y));
    return r;
}
__device__ __forceinline__ void unpack2(unsigned long long v, float& x, float& y) {
    asm("mov.b64 {%0,%1}, %2;" : "=f"(x), "=f"(y) : "l"(v));
}
__device__ __forceinline__ void ffma2(unsigned long long& d, unsigned long long a, unsigned long long b) {
    asm("fma.rn.f32x2 %0, %1, %2, %0;" : "+l"(d) : "l"(a), "l"(b));
}

// ---------- cp.async helpers ----------
__device__ __forceinline__ void cp16(uint32_t saddr, const void* gptr) {
    asm volatile("cp.async.cg.shared.global [%0], [%1], 16;" :: "r"(saddr), "l"(gptr));
}
__device__ __forceinline__ void cp_commit() { asm volatile("cp.async.commit_group;"); }
__device__ __forceinline__ void cp_wait1()  { asm volatile("cp.async.wait_group 1;"); }
__device__ __forceinline__ void cp_wait0()  { asm volatile("cp.async.wait_group 0;"); }
__device__ __forceinline__ uint32_t cvta_s(const void* p) {
    return (uint32_t)__cvta_generic_to_shared(p);
}

// swizzles
__device__ __forceinline__ int swzE(int row) { return ((row>>3) ^ (row>>5)) & 7; }
__device__ __forceinline__ int swzV(int r)   { return ((r>>2)&7) ^ ((r&1)<<2); }

// ---------- weight transpose: WT[k][j] = W[j][k] ----------
__global__ void transpose_w(const float* __restrict__ W0, const float* __restrict__ W1,
                            const float* __restrict__ W2, const float* __restrict__ W3) {
    __shared__ float tile[32][33];
    const float* W = (blockIdx.z == 0) ? W0 : (blockIdx.z == 1) ? W1 : (blockIdx.z == 2) ? W2 : W3;
    float* WT = g_WT[blockIdx.z];
    int x = blockIdx.x*32 + threadIdx.x;
    int y = blockIdx.y*32 + threadIdx.y;
    #pragma unroll
    for (int j = 0; j < 32; j += 8)
        tile[threadIdx.y + j][threadIdx.x] = W[(y + j)*D + x];
    __syncthreads();
    int x2 = blockIdx.y*32 + threadIdx.x;
    int y2 = blockIdx.x*32 + threadIdx.y;
    #pragma unroll
    for (int j = 0; j < 32; j += 8)
        WT[(y2 + j)*D + x2] = tile[threadIdx.x][threadIdx.y + j];
}

// ---------- projection core ----------
__device__ __forceinline__ void proj_core(const float* __restrict__ X,
                                          const float* __restrict__ WT,
                                          float* __restrict__ Y, int r0) {
    __shared__ float sXT[192*33];
    const int tid = threadIdx.x;
    const int w = tid >> 5, lane = tid & 31;

    #pragma unroll
    for (int k = 0; k < 12; k++) {
        int idx = tid + k*128;
        int r = idx / 48, c = idx % 48;
        float4 v = *reinterpret_cast<const float4*>(X + (size_t)(r0 + r)*D + 4*c);
        sXT[(4*c+0)*33 + r] = v.x;
        sXT[(4*c+1)*33 + r] = v.y;
        sXT[(4*c+2)*33 + r] = v.z;
        sXT[(4*c+3)*33 + r] = v.w;
    }
    __syncthreads();

    unsigned long long acc[8][3];
    #pragma unroll
    for (int i = 0; i < 8; i++)
        #pragma unroll
        for (int p = 0; p < 3; p++) acc[i][p] = 0ull;

    #pragma unroll 2
    for (int k = 0; k < 192; k++) {
        const unsigned long long* wrow =
            reinterpret_cast<const unsigned long long*>(WT + k*D + lane*6);
        unsigned long long w0 = wrow[0], w1 = wrow[1], w2 = wrow[2];
        #pragma unroll
        for (int i = 0; i < 8; i++) {
            float xv = sXT[k*33 + w*8 + i];
            unsigned long long x2 = pack2(xv, xv);
            ffma2(acc[i][0], x2, w0);
            ffma2(acc[i][1], x2, w1);
            ffma2(acc[i][2], x2, w2);
        }
    }
    #pragma unroll
    for (int i = 0; i < 8; i++) {
        unsigned long long* dst =
            reinterpret_cast<unsigned long long*>(Y + (size_t)(r0 + w*8 + i)*D + lane*6);
        dst[0] = acc[i][0]; dst[1] = acc[i][1]; dst[2] = acc[i][2];
    }
}

__global__ __launch_bounds__(128, 4) void proj3_kernel(const float* __restrict__ X0,
                                                       const float* __restrict__ X1,
                                                       const float* __restrict__ X2,
                                                       float* __restrict__ Y0,
                                                       float* __restrict__ Y1,
                                                       float* __restrict__ Y2) {
    const int which = blockIdx.y;
    const float* X = (which == 0) ? X0 : (which == 1) ? X1 : X2;
    float*       Y = (which == 0) ? Y0 : (which == 1) ? Y1 : Y2;
    proj_core(X, g_WT[which], Y, blockIdx.x * 32);
}

__global__ __launch_bounds__(128, 4) void proj1_kernel(const float* __restrict__ X,
                                                       float* __restrict__ Y) {
    proj_core(X, g_WT[3], Y, blockIdx.x * 32);
}

// ============================================================================
// logits: E = exp(QK^T + bias, masked), 1/rowsum -> g_Linv.
// Grid (B, S/32) = 256 blocks, 256 threads, 2 CTAs/SM.
// Thread: 8 qi x 4 j. Inner loop reordered (kv[4] outer, single qv broadcast
// inner) to keep live regs ~100 and avoid the 128-reg-cap spills of R4.
// ============================================================================
#define A_SMEM ((32*48 + 64*48)*16)
__global__ __launch_bounds__(256, 2) void logits_kernel(const int* __restrict__ gmask,
                                                        const float* __restrict__ gbias) {
    extern __shared__ float4 smA[];
    float4* sQ = smA;             // 32*48
    float4* sK = smA + 32*48;     // 64*48
    const int tid = threadIdx.x;
    const int b  = blockIdx.x;
    const int q0 = blockIdx.y * TQ;
    const int jg = tid & 15, rg = tid >> 4;
    const int h  = rg >> 2;
    const int qi0 = (rg & 3) * 8;

    const uint32_t sQ_a = cvta_s(sQ);
    const uint32_t sK_a = cvta_s(sK);

    { // prologue: Q + K(0)
        const float* gq = g_q + (size_t)(b*S + q0) * D;
        const float* gk = g_k + (size_t)(b*S) * D;
        #pragma unroll
        for (int k = 0; k < 6; k++) {
            int idx = tid + k*256;
            int r = idx / 48, c = idx - r*48;
            cp16(sQ_a + (r*48 + (c ^ ((r>>2)&7)))*16, gq + (size_t)r*D + c*4);
        }
        #pragma unroll
        for (int k = 0; k < 12; k++) {
            int idx = tid + k*256;
            int r = idx / 48, c = idx - r*48;
            cp16(sK_a + (r*48 + (c ^ ((r>>2)&7)))*16, gk + (size_t)r*D + c*4);
        }
        cp_commit();
    }

    float lsum[8];
    #pragma unroll
    for (int i = 0; i < 8; i++) lsum[i] = 0.f;

    // precomputed smem indices (f4 units)
    int kidx[4], qidx[8];
    #pragma unroll
    for (int m = 0; m < 4; m++) { int r = 4*jg + m; kidx[m] = r*48 + (((r>>2)&7) ^ 0); }
    #pragma unroll
    for (int i = 0; i < 8; i++) { int r = qi0 + i;  qidx[i] = r*48 + (((r>>2)&7) ^ 0); }

    for (int t = 0; t < NT; t++) {
        cp_wait0();
        __syncthreads();

        unsigned long long acc[8][4];
        #pragma unroll
        for (int i = 0; i < 8; i++)
            #pragma unroll
            for (int m = 0; m < 4; m++) acc[i][m] = 0ull;

        #pragma unroll
        for (int ch = 0; ch < 12; ch++) {
            const int cc = h*12 + ch;
            unsigned long long kp[4][2];
            #pragma unroll
            for (int m = 0; m < 4; m++) {
                const int r = 4*jg + m;
                float4 kv = sK[r*48 + (cc ^ ((r>>2)&7))];
                kp[m][0] = reinterpret_cast<const unsigned long long*>(&kv)[0];
                kp[m][1] = reinterpret_cast<const unsigned long long*>(&kv)[1];
            }
            #pragma unroll
            for (int i = 0; i < 8; i++) {
                const int r = qi0 + i;
                float4 qv = sQ[r*48 + (cc ^ ((r>>2)&7))];       // broadcast
                const unsigned long long* qp = reinterpret_cast<const unsigned long long*>(&qv);
                #pragma unroll
                for (int m = 0; m < 4; m++) {
                    ffma2(acc[i][m], qp[0], kp[m][0]);
                    ffma2(acc[i][m], qp[1], kp[m][1]);
                }
            }
        }
        __syncthreads();

        if (t+1 < NT) { // prefetch K(t+1); overlaps the gmem epilogue
            const float* gk = g_k + (size_t)(b*S + (t+1)*TK) * D;
            #pragma unroll
            for (int k = 0; k < 12; k++) {
                int idx = tid + k*256;
                int r = idx / 48, c = idx - r*48;
                cp16(sK_a + (r*48 + (c ^ ((r>>2)&7)))*16, gk + (size_t)r*D + c*4);
            }
            cp_commit();
        }

        // epilogue: mask/bias from gmem, exp, store E
        const int jc = t*TK + 4*jg;
        #pragma unroll
        for (int i = 0; i < 8; i++) {
            const int qi = q0 + qi0 + i;
            int4   mv = *reinterpret_cast<const int4*>(gmask + (size_t)(b*S + qi)*S + jc);
            float4 bv = *reinterpret_cast<const float4*>(gbias + (size_t)(h*S + qi)*S + jc);
            float4 ev;
            float ax, ay;
            unpack2(acc[i][0], ax, ay); ev.x = __expf(mv.x ? ax + ay + bv.x : NEG_INF);
            unpack2(acc[i][1], ax, ay); ev.y = __expf(mv.y ? ax + ay + bv.y : NEG_INF);
            unpack2(acc[i][2], ax, ay); ev.z = __expf(mv.z ? ax + ay + bv.z : NEG_INF);
            unpack2(acc[i][3], ax, ay); ev.w = __expf(mv.w ? ax + ay + bv.w : NEG_INF);
            lsum[i] += (ev.x + ev.y) + (ev.z + ev.w);
            *reinterpret_cast<float4*>(g_E + (size_t)((b*H + h)*S + qi)*S + jc) = ev;
        }
        (void)kidx; (void)qidx;
    }

    #pragma unroll
    for (int i = 0; i < 8; i++) {
        float v = lsum[i];
        v += __shfl_xor_sync(0xffffffffu, v, 1);
        v += __shfl_xor_sync(0xffffffffu, v, 2);
        v += __shfl_xor_sync(0xffffffffu, v, 4);
        v += __shfl_xor_sync(0xffffffffu, v, 8);
        if (jg == 0) g_Linv[(b*H + h)*S + q0 + qi0 + i] = 1.0f / v;
    }
}

// ============================================================================
// pv: O = (E*Linv) @ V -> g_ctx, fused head-mean -> om.
// Grid (B, S/32), 128 threads. Thread: h=tid>>5, qg=(tid>>3)&3 (8 qi),
// pg=(tid>>1)&3 (3 f4 cols), jh=tid&1 (j parity, shuffle-reduced).
// E consumed via LDS.128 (one per row x 4-j chunk) + FSEL component select:
// 112 LDS/tile instead of 352, swizzle math hoisted.
// ============================================================================
#define PV_SMEM (2*128*32*4 + 2*32*48*16 + 128*4)
__global__ __launch_bounds__(128, 2) void pv_kernel(float* __restrict__ om) {
    extern __shared__ float smP[];
    float*  sE = smP;                                    // 2 x 4096 floats
    float4* sV = reinterpret_cast<float4*>(smP + 8192);  // 2 x 1536 f4
    float*  sLinv = smP + 8192 + 12288;                  // 128
    const int tid = threadIdx.x;
    const int b  = blockIdx.x;
    const int q0 = blockIdx.y * TQ;
    const int h  = tid >> 5;
    const int qg = (tid >> 3) & 3;
    const int pg = (tid >> 1) & 3;
    const int jh = tid & 1;
    const int rb = h*32 + qg*8;
    const int c0 = h*12 + pg*3;
    // head-mean lane map: within-warp rows differ in bits {3,4} -> swzE-covered
    const int hm_qi = ((tid & 31) >> 3) * 8 + (tid >> 5);
    const int hm_c4 = tid & 7;

    const uint32_t sE_a = cvta_s(sE);
    const uint32_t sV_a = cvta_s(sV);

    { // prologue: E(0) + V(0)
        #pragma unroll
        for (int k = 0; k < 8; k++) {
            int idx = tid + k*128;
            int row = idx >> 3, c4 = idx & 7;
            const float* src = g_E + (size_t)((b*H + (row>>5))*S + q0 + (row&31))*S + c4*4;
            cp16(sE_a + (row*32 + ((c4 ^ swzE(row))<<2))*4, src);
        }
        #pragma unroll
        for (int k = 0; k < 12; k++) {
            int idx = tid + k*128;
            int r = idx / 48, c = idx - r*48;
            cp16(sV_a + (r*48 + (c ^ swzV(r)))*16, g_v + (size_t)(b*S + r)*D + c*4);
        }
        cp_commit();
        sLinv[tid] = g_Linv[(b*H + (tid>>5))*S + q0 + (tid & 31)];
    }

    int ebase[8], eswz[8];
    #pragma unroll
    for (int i = 0; i < 8; i++) { ebase[i] = (rb+i)*32; eswz[i] = swzE(rb+i); }

    unsigned long long acc[8][6];
    #pragma unroll
    for (int i = 0; i < 8; i++)
        #pragma unroll
        for (int p = 0; p < 6; p++) acc[i][p] = 0ull;

    for (int t = 0; t < NT2; t++) {
        if (t+1 < NT2) { // prefetch E(t+1)+V(t+1)
            const int bo = ((t+1)&1);
            #pragma unroll
            for (int k = 0; k < 8; k++) {
                int idx = tid + k*128;
                int row = idx >> 3, c4 = idx & 7;
                const float* src = g_E + (size_t)((b*H + (row>>5))*S + q0 + (row&31))*S + (t+1)*TKV + c4*4;
                cp16(sE_a + (bo*4096 + row*32 + ((c4 ^ swzE(row))<<2))*4, src);
            }
            #pragma unroll
            for (int k = 0; k < 12; k++) {
                int idx = tid + k*128;
                int r = idx / 48, c = idx - r*48;
                cp16(sV_a + (bo*1536 + r*48 + (c ^ swzV(r)))*16,
                     g_v + (size_t)(b*S + (t+1)*TKV + r)*D + c*4);
            }
            cp_commit();
            cp_wait1();
        } else {
            cp_wait0();
        }
        __syncthreads();
        const float*  Et = sE + (t&1)*4096;
        const float4* Vt = sV + (t&1)*1536;

        { // head-mean output tile (conflict-free lane map)
            #pragma unroll
            for (int k = 0; k < 2; k++) {
                const int qi = hm_qi + 4*k;
                float4 a0 = *reinterpret_cast<const float4*>(&Et[(0*32+qi)*32 + ((hm_c4 ^ swzE(0*32+qi))<<2)]);
                float4 a1 = *reinterpret_cast<const float4*>(&Et[(1*32+qi)*32 + ((hm_c4 ^ swzE(1*32+qi))<<2)]);
                float4 a2 = *reinterpret_cast<const float4*>(&Et[(2*32+qi)*32 + ((hm_c4 ^ swzE(2*32+qi))<<2)]);
                float4 a3 = *reinterpret_cast<const float4*>(&Et[(3*32+qi)*32 + ((hm_c4 ^ swzE(3*32+qi))<<2)]);
                float l0 = sLinv[qi], l1 = sLinv[32+qi], l2 = sLinv[64+qi], l3 = sLinv[96+qi];
                float4 r;
                r.x = 0.25f*(a0.x*l0 + a1.x*l1 + a2.x*l2 + a3.x*l3);
                r.y = 0.25f*(a0.y*l0 + a1.y*l1 + a2.y*l2 + a3.y*l3);
                r.z = 0.25f*(a0.z*l0 + a1.z*l1 + a2.z*l2 + a3.z*l3);
                r.w = 0.25f*(a0.w*l0 + a1.w*l1 + a2.w*l2 + a3.w*l3);
                *reinterpret_cast<float4*>(om + (size_t)(b*S + q0 + qi)*S + t*TKV + hm_c4*4) = r;
            }
        }

        // PV accumulation: per 4-j chunk, vector E loads + component select
        #pragma unroll
        for (int c4j = 0; c4j < 8; c4j++) {
            float4 e4[8];
            #pragma unroll
            for (int i = 0; i < 8; i++)
                e4[i] = *reinterpret_cast<const float4*>(&Et[ebase[i] + ((c4j ^ eswz[i])<<2)]);
            #pragma unroll
            for (int u = 0; u < 2; u++) {
                const int j = 4*c4j + jh + 2*u;
                const int swv = swzV(j);
                float4 v0 = Vt[j*48 + ((c0+0) ^ swv)];
                float4 v1 = Vt[j*48 + ((c0+1) ^ swv)];
                float4 v2 = Vt[j*48 + ((c0+2) ^ swv)];
                const unsigned long long* p0 = reinterpret_cast<const unsigned long long*>(&v0);
                const unsigned long long* p1 = reinterpret_cast<const unsigned long long*>(&v1);
                const unsigned long long* p2 = reinterpret_cast<const unsigned long long*>(&v2);
                #pragma unroll
                for (int i = 0; i < 8; i++) {
                    float e = (u == 0) ? (jh ? e4[i].y : e4[i].x)
                                       : (jh ? e4[i].w : e4[i].z);
                    unsigned long long e2 = pack2(e, e);
                    ffma2(acc[i][0], e2, p0[0]); ffma2(acc[i][1], e2, p0[1]);
                    ffma2(acc[i][2], e2, p1[0]); ffma2(acc[i][3], e2, p1[1]);
                    ffma2(acc[i][4], e2, p2[0]); ffma2(acc[i][5], e2, p2[1]);
                }
            }
        }
        __syncthreads();   // buffers free before next prefetch overwrite
    }

    // reduce jh pairs, scale, store ctx
    #pragma unroll
    for (int i = 0; i < 8; i++) {
        const int qrow = qg*8 + i;
        const float linv = sLinv[h*32 + qrow];
        float xs[6], ys[6];
        #pragma unroll
        for (int p = 0; p < 6; p++) {
            float x, y; unpack2(acc[i][p], x, y);
            x += __shfl_xor_sync(0xffffffffu, x, 1);
            y += __shfl_xor_sync(0xffffffffu, y, 1);
            xs[p] = x * linv; ys[p] = y * linv;
        }
        if (jh == 0) {
            float4* dst = reinterpret_cast<float4*>(g_ctx + (size_t)(b*S + q0 + qrow)*D + h*48 + pg*12);
            #pragma unroll
            for (int m = 0; m < 3; m++) {
                float4 o; o.x = xs[2*m]; o.y = ys[2*m]; o.z = xs[2*m+1]; o.w = ys[2*m+1];
                dst[m] = o;
            }
        }
    }
}

extern "C" void kernel_launch(void* const* d_in, const int* in_sizes, int n_in,
                              void* d_out, int out_size) {
    (void)in_sizes; (void)n_in; (void)out_size;
    const float* query = (const float*)d_in[0];
    const float* key   = (const float*)d_in[1];
    const float* value = (const float*)d_in[2];
    const int*   mask  = (const int*)  d_in[3];
    const float* bias  = (const float*)d_in[4];
    const float* Wq    = (const float*)d_in[5];
    const float* Wk    = (const float*)d_in[6];
    const float* Wv    = (const float*)d_in[7];
    const float* Wo    = (const float*)d_in[8];

    float* out = (float*)d_out;                 // [B,S,D]
    float* om  = out + B*S*D;                   // [B,S,S] mean weights

    float *pq, *pk, *pv, *pctx;
    cudaGetSymbolAddress((void**)&pq,   g_q);
    cudaGetSymbolAddress((void**)&pk,   g_k);
    cudaGetSymbolAddress((void**)&pv,   g_v);
    cudaGetSymbolAddress((void**)&pctx, g_ctx);

    cudaFuncSetAttribute(logits_kernel, cudaFuncAttributeMaxDynamicSharedMemorySize, A_SMEM);
    cudaFuncSetAttribute(pv_kernel,     cudaFuncAttributeMaxDynamicSharedMemorySize, PV_SMEM);

    transpose_w<<<dim3(6,6,4), dim3(32,8)>>>(Wq, Wk, Wv, Wo);
    proj3_kernel<<<dim3(256,3), 128>>>(query, key, value, pq, pk, pv);
    logits_kernel<<<dim3(B, S/TQ), 256, A_SMEM>>>(mask, bias);
    pv_kernel<<<dim3(B, S/TQ), 128, PV_SMEM>>>(om);
    proj1_kernel<<<dim3(256,1), 128>>>(pctx, out);
}

// round 7
// speedup vs baseline: 2.3149x; 1.1292x over previous
#include <cuda_runtime.h>
#include <cuda_bf16.h>
#include <cstdint>

#define B 4
#define S 2048
#define H 4
#define DH 48
#define D 192
#define TQ 32
#define TKV 32
#define NT2 (S/TKV)
#define NEG_INF -1000000000.0f

// Scratch
__device__ float g_v[B*S*D];
__device__ float g_ctx[B*S*D];
__device__ float g_E[(size_t)B*H*S*S];     // 256MB unnormalized exp(logits)
__device__ float g_Linv[B*H*S];
__device__ float g_WT[4][D*D];             // pre-transposed weights [k][j]
__device__ __nv_bfloat16 g_qh[B*H*S*DH];   // Q head-major bf16 hi
__device__ __nv_bfloat16 g_ql[B*H*S*DH];   // Q bf16 lo (residual)
__device__ __nv_bfloat16 g_kh[B*H*S*DH];
__device__ __nv_bfloat16 g_kl[B*H*S*DH];

// ---------- packed fp32x2 helpers ----------
__device__ __forceinline__ unsigned long long pack2(float x, float y) {
    unsigned long long r;
    asm("mov.b64 %0, {%1,%2};" : "=l"(r) : "f"(x), "f"(y));
    return r;
}
__device__ __forceinline__ void unpack2(unsigned long long v, float& x, float& y) {
    asm("mov.b64 {%0,%1}, %2;" : "=f"(x), "=f"(y) : "l"(v));
}
__device__ __forceinline__ void ffma2(unsigned long long& d, unsigned long long a, unsigned long long b) {
    asm("fma.rn.f32x2 %0, %1, %2, %0;" : "+l"(d) : "l"(a), "l"(b));
}

// ---------- cp.async helpers ----------
__device__ __forceinline__ void cp16(uint32_t saddr, const void* gptr) {
    asm volatile("cp.async.cg.shared.global [%0], [%1], 16;" :: "r"(saddr), "l"(gptr));
}
__device__ __forceinline__ void cp_commit() { asm volatile("cp.async.commit_group;"); }
__device__ __forceinline__ void cp_wait1()  { asm volatile("cp.async.wait_group 1;"); }
__device__ __forceinline__ void cp_wait0()  { asm volatile("cp.async.wait_group 0;"); }
__device__ __forceinline__ uint32_t cvta_s(const void* p) {
    return (uint32_t)__cvta_generic_to_shared(p);
}

// ---------- mma.sync / ldmatrix helpers (sm_80 baseline, no 'a' features) ----------
__device__ __forceinline__ void ldsm4(uint32_t addr, uint32_t* r) {
    asm volatile("ldmatrix.sync.aligned.m8n8.x4.shared.b16 {%0,%1,%2,%3}, [%4];"
                 : "=r"(r[0]), "=r"(r[1]), "=r"(r[2]), "=r"(r[3]) : "r"(addr));
}
__device__ __forceinline__ void mma16816(float* c, const uint32_t* a, const uint32_t* b) {
    asm volatile("mma.sync.aligned.m16n8k16.row.col.f32.bf16.bf16.f32 "
                 "{%0,%1,%2,%3}, {%4,%5,%6,%7}, {%8,%9}, {%0,%1,%2,%3};"
                 : "+f"(c[0]), "+f"(c[1]), "+f"(c[2]), "+f"(c[3])
                 : "r"(a[0]), "r"(a[1]), "r"(a[2]), "r"(a[3]), "r"(b[0]), "r"(b[1]));
}

// swizzles (scalar-path pv)
__device__ __forceinline__ int swzE(int row) { return ((row>>3) ^ (row>>5)) & 7; }
__device__ __forceinline__ int swzV(int r)   { return ((r>>2)&7) ^ ((r&1)<<2); }

// ---------- weight transpose ----------
__global__ void transpose_w(const float* __restrict__ W0, const float* __restrict__ W1,
                            const float* __restrict__ W2, const float* __restrict__ W3) {
    __shared__ float tile[32][33];
    const float* W = (blockIdx.z == 0) ? W0 : (blockIdx.z == 1) ? W1 : (blockIdx.z == 2) ? W2 : W3;
    float* WT = g_WT[blockIdx.z];
    int x = blockIdx.x*32 + threadIdx.x;
    int y = blockIdx.y*32 + threadIdx.y;
    #pragma unroll
    for (int j = 0; j < 32; j += 8)
        tile[threadIdx.y + j][threadIdx.x] = W[(y + j)*D + x];
    __syncthreads();
    int x2 = blockIdx.y*32 + threadIdx.x;
    int y2 = blockIdx.x*32 + threadIdx.y;
    #pragma unroll
    for (int j = 0; j < 32; j += 8)
        WT[(y2 + j)*D + x2] = tile[threadIdx.x][threadIdx.y + j];
}

// ---------- projection core ----------
template<bool BF16OUT>
__device__ __forceinline__ void proj_core(const float* __restrict__ X,
                                          const float* __restrict__ WT,
                                          float* __restrict__ Yf,
                                          __nv_bfloat16* __restrict__ Yh,
                                          __nv_bfloat16* __restrict__ Yl,
                                          int r0) {
    __shared__ float sXT[192*33];
    const int tid = threadIdx.x;
    const int w = tid >> 5, lane = tid & 31;

    #pragma unroll
    for (int k = 0; k < 12; k++) {
        int idx = tid + k*128;
        int r = idx / 48, c = idx % 48;
        float4 v = *reinterpret_cast<const float4*>(X + (size_t)(r0 + r)*D + 4*c);
        sXT[(4*c+0)*33 + r] = v.x;
        sXT[(4*c+1)*33 + r] = v.y;
        sXT[(4*c+2)*33 + r] = v.z;
        sXT[(4*c+3)*33 + r] = v.w;
    }
    __syncthreads();

    unsigned long long acc[8][3];
    #pragma unroll
    for (int i = 0; i < 8; i++)
        #pragma unroll
        for (int p = 0; p < 3; p++) acc[i][p] = 0ull;

    #pragma unroll 2
    for (int k = 0; k < 192; k++) {
        const unsigned long long* wrow =
            reinterpret_cast<const unsigned long long*>(WT + k*D + lane*6);
        unsigned long long w0 = wrow[0], w1 = wrow[1], w2 = wrow[2];
        #pragma unroll
        for (int i = 0; i < 8; i++) {
            float xv = sXT[k*33 + w*8 + i];
            unsigned long long x2 = pack2(xv, xv);
            ffma2(acc[i][0], x2, w0);
            ffma2(acc[i][1], x2, w1);
            ffma2(acc[i][2], x2, w2);
        }
    }
    #pragma unroll
    for (int i = 0; i < 8; i++) {
        const int row = r0 + w*8 + i;      // b*S + s
        if (BF16OUT) {
            const int bb = row >> 11, s = row & 2047;
            const int hh = lane >> 3, c0 = (lane & 7)*6;
            size_t base = ((size_t)(bb*H + hh)*S + s)*DH + c0;
            #pragma unroll
            for (int m = 0; m < 3; m++) {
                float x, y; unpack2(acc[i][m], x, y);
                __nv_bfloat16 hx = __float2bfloat16(x);
                __nv_bfloat16 hy = __float2bfloat16(y);
                float lx = x - __bfloat162float(hx);
                float ly = y - __bfloat162float(hy);
                __nv_bfloat162 hv; hv.x = hx; hv.y = hy;
                __nv_bfloat162 lv; lv.x = __float2bfloat16(lx); lv.y = __float2bfloat16(ly);
                *reinterpret_cast<__nv_bfloat162*>(Yh + base + 2*m) = hv;
                *reinterpret_cast<__nv_bfloat162*>(Yl + base + 2*m) = lv;
            }
        } else {
            unsigned long long* dst =
                reinterpret_cast<unsigned long long*>(Yf + (size_t)row*D + lane*6);
            dst[0] = acc[i][0]; dst[1] = acc[i][1]; dst[2] = acc[i][2];
        }
    }
}

__global__ __launch_bounds__(128, 4) void proj3_kernel(const float* __restrict__ Xq,
                                                       const float* __restrict__ Xk,
                                                       const float* __restrict__ Xv) {
    const int which = blockIdx.y;
    const int r0 = blockIdx.x * 32;
    if (which == 2)      proj_core<false>(Xv, g_WT[2], g_v, nullptr, nullptr, r0);
    else if (which == 0) proj_core<true >(Xq, g_WT[0], nullptr, g_qh, g_ql, r0);
    else                 proj_core<true >(Xk, g_WT[1], nullptr, g_kh, g_kl, r0);
}

__global__ __launch_bounds__(128, 4) void proj1_kernel(const float* __restrict__ X,
                                                       float* __restrict__ Y) {
    proj_core<false>(X, g_WT[3], Y, nullptr, nullptr, blockIdx.x * 32);
}

// ============================================================================
// logits_mma: E = exp(QK^T + bias, masked) via mma.sync bf16 (hixhi + hixlo +
// loxhi), rowsums -> g_Linv. Block (bh, q-tile of 64), 256 threads (8 warps:
// 2 q-subtiles x 4 j-subtiles of 32). Loops 16 j-tiles of 128, K double-
// buffered via cp.async. Q-hi fragments persistent in registers.
// smem rows padded to 128B with (chunk ^ (row&7)) swizzle -> ldmatrix
// conflict-free.
// ============================================================================
#define OFF_QH 0
#define OFF_QL 8192
#define OFF_KH 16384
#define OFF_KL 49152
#define OFF_SUM 81920
#define SMEM_LG (OFF_SUM + 64*4*4)

__global__ __launch_bounds__(256, 2) void logits_mma(const int* __restrict__ gmask,
                                                     const float* __restrict__ gbias) {
    extern __shared__ char smem[];
    const uint32_t sb = cvta_s(smem);
    float (*sums)[4] = reinterpret_cast<float(*)[4]>(smem + OFF_SUM);
    const int tid = threadIdx.x;
    const int warp = tid >> 5, lane = tid & 31;
    const int bh = blockIdx.x;              // b*H + h
    const int b  = bh >> 2, h = bh & 3;
    const int q0 = blockIdx.y * 64;
    const int qw = (warp >> 2) * 32;        // warp q-subtile
    const int jw = (warp & 3) * 32;         // warp j-subtile

    { // prologue loads: Q hi/lo (64 rows) + K(0) hi/lo (128 rows)
        const __nv_bfloat16* qh = g_qh + ((size_t)bh*S + q0)*DH;
        const __nv_bfloat16* ql = g_ql + ((size_t)bh*S + q0)*DH;
        #pragma unroll
        for (int k = 0; k < 2; k++) {
            int idx = tid + k*256;           // wait: 384 chunks -> k<2 covers 512, guard
            if (idx < 384) {
                int r = idx / 6, c = idx % 6;
                uint32_t off = r*128 + ((c ^ (r&7))<<4);
                cp16(sb + OFF_QH + off, qh + r*DH + c*8);
                cp16(sb + OFF_QL + off, ql + r*DH + c*8);
            }
        }
        const __nv_bfloat16* kh = g_kh + (size_t)bh*S*DH;
        const __nv_bfloat16* kl = g_kl + (size_t)bh*S*DH;
        #pragma unroll
        for (int k = 0; k < 3; k++) {
            int idx = tid + k*256;           // 768 chunks
            int r = idx / 6, c = idx % 6;
            uint32_t off = r*128 + ((c ^ (r&7))<<4);
            cp16(sb + OFF_KH + off, kh + r*DH + c*8);
            cp16(sb + OFF_KL + off, kl + r*DH + c*8);
        }
        cp_commit();
    }
    cp_wait0();
    __syncthreads();

    // persistent Q-hi fragments: ah[mi][ks][4]
    uint32_t ah[2][3][4];
    #pragma unroll
    for (int mi = 0; mi < 2; mi++)
        #pragma unroll
        for (int ks = 0; ks < 3; ks++) {
            int r = qw + mi*16 + (lane & 7) + ((lane >> 3) & 1)*8;
            int c = ks*2 + (lane >> 4);
            ldsm4(sb + OFF_QH + r*128 + ((c ^ (r&7))<<4), ah[mi][ks]);
        }

    float lsum[4] = {0.f, 0.f, 0.f, 0.f};   // [mi*2 + h2]

    for (int jt = 0; jt < 16; jt++) {
        const uint32_t kbH = sb + OFF_KH + (jt & 1)*16384;
        const uint32_t kbL = sb + OFF_KL + (jt & 1)*16384;

        if (jt + 1 < 16) { // prefetch K(jt+1) into the other buffer
            const uint32_t nH = sb + OFF_KH + ((jt+1) & 1)*16384;
            const uint32_t nL = sb + OFF_KL + ((jt+1) & 1)*16384;
            const __nv_bfloat16* kh = g_kh + ((size_t)bh*S + (jt+1)*128)*DH;
            const __nv_bfloat16* kl = g_kl + ((size_t)bh*S + (jt+1)*128)*DH;
            #pragma unroll
            for (int k = 0; k < 3; k++) {
                int idx = tid + k*256;
                int r = idx / 6, c = idx % 6;
                uint32_t off = r*128 + ((c ^ (r&7))<<4);
                cp16(nH + off, kh + r*DH + c*8);
                cp16(nL + off, kl + r*DH + c*8);
            }
            cp_commit();
        }

        float acc[2][4][4];
        #pragma unroll
        for (int mi = 0; mi < 2; mi++)
            #pragma unroll
            for (int nj = 0; nj < 4; nj++)
                #pragma unroll
                for (int p = 0; p < 4; p++) acc[mi][nj][p] = 0.f;

        #pragma unroll
        for (int ks = 0; ks < 3; ks++) {
            uint32_t bhf[2][4], blf[2][4], alf[2][4];
            #pragma unroll
            for (int jj = 0; jj < 2; jj++) {
                int r = jw + jj*16 + (lane & 7) + (lane >> 4)*8;
                int c = ks*2 + ((lane >> 3) & 1);
                uint32_t off = r*128 + ((c ^ (r&7))<<4);
                ldsm4(kbH + off, bhf[jj]);
                ldsm4(kbL + off, blf[jj]);
            }
            #pragma unroll
            for (int mi = 0; mi < 2; mi++) {
                int r = qw + mi*16 + (lane & 7) + ((lane >> 3) & 1)*8;
                int c = ks*2 + (lane >> 4);
                ldsm4(sb + OFF_QL + r*128 + ((c ^ (r&7))<<4), alf[mi]);
            }
            #pragma unroll
            for (int mi = 0; mi < 2; mi++)
                #pragma unroll
                for (int jj = 0; jj < 2; jj++)
                    #pragma unroll
                    for (int sub = 0; sub < 2; sub++) {
                        float* a = acc[mi][jj*2 + sub];
                        mma16816(a, ah[mi][ks], &bhf[jj][sub*2]);   // hi*hi
                        mma16816(a, ah[mi][ks], &blf[jj][sub*2]);   // hi*lo
                        mma16816(a, alf[mi],    &bhf[jj][sub*2]);   // lo*hi
                    }
        }
        __syncthreads();   // all warps done reading K buffer (jt&1)

        // epilogue: mask/bias/exp/E-store + rowsum partials, fragment layout
        const int jbase = jt*128 + jw + (lane & 3)*2;
        #pragma unroll
        for (int mi = 0; mi < 2; mi++)
            #pragma unroll
            for (int h2 = 0; h2 < 2; h2++) {
                const int qrow = q0 + qw + mi*16 + h2*8 + (lane >> 2);
                const int*   mrow = gmask + (size_t)(b*S + qrow)*S + jbase;
                const float* brow = gbias + (size_t)(h*S + qrow)*S + jbase;
                float*       erow = g_E + ((size_t)bh*S + qrow)*S + jbase;
                float ls = 0.f;
                #pragma unroll
                for (int nj = 0; nj < 4; nj++) {
                    int2   mv = *reinterpret_cast<const int2*>(mrow + nj*8);
                    float2 bv = *reinterpret_cast<const float2*>(brow + nj*8);
                    float e0 = __expf(mv.x ? acc[mi][nj][h2*2+0] + bv.x : NEG_INF);
                    float e1 = __expf(mv.y ? acc[mi][nj][h2*2+1] + bv.y : NEG_INF);
                    float2 ev; ev.x = e0; ev.y = e1;
                    *reinterpret_cast<float2*>(erow + nj*8) = ev;
                    ls += e0 + e1;
                }
                lsum[mi*2 + h2] += ls;
            }

        cp_wait0();        // K(jt+1) landed before next iteration reads it
    }

    // rowsum reduce: quad lanes share rows -> shfl; stage per-jwarp partials
    #pragma unroll
    for (int k = 0; k < 4; k++) {
        float v = lsum[k];
        v += __shfl_xor_sync(0xffffffffu, v, 1);
        v += __shfl_xor_sync(0xffffffffu, v, 2);
        if ((lane & 3) == 0)
            sums[qw + (k >> 1)*16 + (k & 1)*8 + (lane >> 2)][warp & 3] = v;
    }
    __syncthreads();
    if (tid < 64) {
        float L = sums[tid][0] + sums[tid][1] + sums[tid][2] + sums[tid][3];
        g_Linv[(size_t)bh*S + q0 + tid] = 1.0f / L;
    }
}

// ============================================================================
// pv: O = (E*Linv) @ V -> g_ctx, fused head-mean -> om. (R5 scalar kernel)
// ============================================================================
#define PV_SMEM (2*128*32*4 + 2*32*48*16 + 128*4)
__global__ __launch_bounds__(128, 2) void pv_kernel(float* __restrict__ om) {
    extern __shared__ float smP[];
    float*  sE = smP;
    float4* sV = reinterpret_cast<float4*>(smP + 8192);
    float*  sLinv = smP + 8192 + 12288;
    const int tid = threadIdx.x;
    const int b  = blockIdx.x;
    const int q0 = blockIdx.y * TQ;
    const int h  = tid >> 5;
    const int qg = (tid >> 3) & 3;
    const int pg = (tid >> 1) & 3;
    const int jh = tid & 1;
    const int rb = h*32 + qg*8;
    const int c0 = h*12 + pg*3;
    const int hm_qi = ((tid & 31) >> 3) * 8 + (tid >> 5);
    const int hm_c4 = tid & 7;

    const uint32_t sE_a = cvta_s(sE);
    const uint32_t sV_a = cvta_s(sV);

    {
        #pragma unroll
        for (int k = 0; k < 8; k++) {
            int idx = tid + k*128;
            int row = idx >> 3, c4 = idx & 7;
            const float* src = g_E + (size_t)((b*H + (row>>5))*S + q0 + (row&31))*S + c4*4;
            cp16(sE_a + (row*32 + ((c4 ^ swzE(row))<<2))*4, src);
        }
        #pragma unroll
        for (int k = 0; k < 12; k++) {
            int idx = tid + k*128;
            int r = idx / 48, c = idx - r*48;
            cp16(sV_a + (r*48 + (c ^ swzV(r)))*16, g_v + (size_t)(b*S + r)*D + c*4);
        }
        cp_commit();
        sLinv[tid] = 1.0f / (1.0f / g_Linv[(size_t)(b*H + (tid>>5))*S + q0 + (tid & 31)]);
        sLinv[tid] = g_Linv[(size_t)(b*H + (tid>>5))*S + q0 + (tid & 31)];
    }

    int ebase[8], eswz[8];
    #pragma unroll
    for (int i = 0; i < 8; i++) { ebase[i] = (rb+i)*32; eswz[i] = swzE(rb+i); }

    unsigned long long acc[8][6];
    #pragma unroll
    for (int i = 0; i < 8; i++)
        #pragma unroll
        for (int p = 0; p < 6; p++) acc[i][p] = 0ull;

    for (int t = 0; t < NT2; t++) {
        if (t+1 < NT2) {
            const int bo = ((t+1)&1);
            #pragma unroll
            for (int k = 0; k < 8; k++) {
                int idx = tid + k*128;
                int row = idx >> 3, c4 = idx & 7;
                const float* src = g_E + (size_t)((b*H + (row>>5))*S + q0 + (row&31))*S + (t+1)*TKV + c4*4;
                cp16(sE_a + (bo*4096 + row*32 + ((c4 ^ swzE(row))<<2))*4, src);
            }
            #pragma unroll
            for (int k = 0; k < 12; k++) {
                int idx = tid + k*128;
                int r = idx / 48, c = idx - r*48;
                cp16(sV_a + (bo*1536 + r*48 + (c ^ swzV(r)))*16,
                     g_v + (size_t)(b*S + (t+1)*TKV + r)*D + c*4);
            }
            cp_commit();
            cp_wait1();
        } else {
            cp_wait0();
        }
        __syncthreads();
        const float*  Et = sE + (t&1)*4096;
        const float4* Vt = sV + (t&1)*1536;

        {
            #pragma unroll
            for (int k = 0; k < 2; k++) {
                const int qi = hm_qi + 4*k;
                float4 a0 = *reinterpret_cast<const float4*>(&Et[(0*32+qi)*32 + ((hm_c4 ^ swzE(0*32+qi))<<2)]);
                float4 a1 = *reinterpret_cast<const float4*>(&Et[(1*32+qi)*32 + ((hm_c4 ^ swzE(1*32+qi))<<2)]);
                float4 a2 = *reinterpret_cast<const float4*>(&Et[(2*32+qi)*32 + ((hm_c4 ^ swzE(2*32+qi))<<2)]);
                float4 a3 = *reinterpret_cast<const float4*>(&Et[(3*32+qi)*32 + ((hm_c4 ^ swzE(3*32+qi))<<2)]);
                float l0 = sLinv[qi], l1 = sLinv[32+qi], l2 = sLinv[64+qi], l3 = sLinv[96+qi];
                float4 r;
                r.x = 0.25f*(a0.x*l0 + a1.x*l1 + a2.x*l2 + a3.x*l3);
                r.y = 0.25f*(a0.y*l0 + a1.y*l1 + a2.y*l2 + a3.y*l3);
                r.z = 0.25f*(a0.z*l0 + a1.z*l1 + a2.z*l2 + a3.z*l3);
                r.w = 0.25f*(a0.w*l0 + a1.w*l1 + a2.w*l2 + a3.w*l3);
                *reinterpret_cast<float4*>(om + (size_t)(b*S + q0 + qi)*S + t*TKV + hm_c4*4) = r;
            }
        }

        #pragma unroll
        for (int c4j = 0; c4j < 8; c4j++) {
            float4 e4[8];
            #pragma unroll
            for (int i = 0; i < 8; i++)
                e4[i] = *reinterpret_cast<const float4*>(&Et[ebase[i] + ((c4j ^ eswz[i])<<2)]);
            #pragma unroll
            for (int u = 0; u < 2; u++) {
                const int j = 4*c4j + jh + 2*u;
                const int swv = swzV(j);
                float4 v0 = Vt[j*48 + ((c0+0) ^ swv)];
                float4 v1 = Vt[j*48 + ((c0+1) ^ swv)];
                float4 v2 = Vt[j*48 + ((c0+2) ^ swv)];
                const unsigned long long* p0 = reinterpret_cast<const unsigned long long*>(&v0);
                const unsigned long long* p1 = reinterpret_cast<const unsigned long long*>(&v1);
                const unsigned long long* p2 = reinterpret_cast<const unsigned long long*>(&v2);
                #pragma unroll
                for (int i = 0; i < 8; i++) {
                    float e = (u == 0) ? (jh ? e4[i].y : e4[i].x)
                                       : (jh ? e4[i].w : e4[i].z);
                    unsigned long long e2 = pack2(e, e);
                    ffma2(acc[i][0], e2, p0[0]); ffma2(acc[i][1], e2, p0[1]);
                    ffma2(acc[i][2], e2, p1[0]); ffma2(acc[i][3], e2, p1[1]);
                    ffma2(acc[i][4], e2, p2[0]); ffma2(acc[i][5], e2, p2[1]);
                }
            }
        }
        __syncthreads();
    }

    #pragma unroll
    for (int i = 0; i < 8; i++) {
        const int qrow = qg*8 + i;
        const float linv = sLinv[h*32 + qrow];
        float xs[6], ys[6];
        #pragma unroll
        for (int p = 0; p < 6; p++) {
            float x, y; unpack2(acc[i][p], x, y);
            x += __shfl_xor_sync(0xffffffffu, x, 1);
            y += __shfl_xor_sync(0xffffffffu, y, 1);
            xs[p] = x * linv; ys[p] = y * linv;
        }
        if (jh == 0) {
            float4* dst = reinterpret_cast<float4*>(g_ctx + (size_t)(b*S + q0 + qrow)*D + h*48 + pg*12);
            #pragma unroll
            for (int m = 0; m < 3; m++) {
                float4 o; o.x = xs[2*m]; o.y = ys[2*m]; o.z = xs[2*m+1]; o.w = ys[2*m+1];
                dst[m] = o;
            }
        }
    }
}

extern "C" void kernel_launch(void* const* d_in, const int* in_sizes, int n_in,
                              void* d_out, int out_size) {
    (void)in_sizes; (void)n_in; (void)out_size;
    const float* query = (const float*)d_in[0];
    const float* key   = (const float*)d_in[1];
    const float* value = (const float*)d_in[2];
    const int*   mask  = (const int*)  d_in[3];
    const float* bias  = (const float*)d_in[4];
    const float* Wq    = (const float*)d_in[5];
    const float* Wk    = (const float*)d_in[6];
    const float* Wv    = (const float*)d_in[7];
    const float* Wo    = (const float*)d_in[8];

    float* out = (float*)d_out;                 // [B,S,D]
    float* om  = out + B*S*D;                   // [B,S,S] mean weights

    float *pctx;
    cudaGetSymbolAddress((void**)&pctx, g_ctx);

    cudaFuncSetAttribute(logits_mma, cudaFuncAttributeMaxDynamicSharedMemorySize, SMEM_LG);
    cudaFuncSetAttribute(pv_kernel,  cudaFuncAttributeMaxDynamicSharedMemorySize, PV_SMEM);

    transpose_w<<<dim3(6,6,4), dim3(32,8)>>>(Wq, Wk, Wv, Wo);
    proj3_kernel<<<dim3(256,3), 128>>>(query, key, value);
    logits_mma<<<dim3(B*H, S/64), 256, SMEM_LG>>>(mask, bias);
    pv_kernel<<<dim3(B, S/TQ), 128, PV_SMEM>>>(om);
    proj1_kernel<<<dim3(256,1), 128>>>(pctx, out);
}